// round 4
// baseline (speedup 1.0000x reference)
#include <cuda_runtime.h>

#define B_   8
#define T_   2048
#define H_   512
#define V_   32000
#define OUTC (V_ + T_)        // 34048
#define NROWS (V_ + B_ * T_)  // 48384

#define BM 128
#define BN 128
#define BK 16
#define LDS_ 132              // BM + 4 pad (conflict-free, keeps 16B alignment: 132 % 4 == 0)

// scratch: q_proj[b][k] + b1[k]
__device__ float g_qb[B_ * H_];

// ---------------------------------------------------------------------------
// Kernel 1: qb[b][k] = sum_h input_embeds[b,h] * w1[k, h] + b1[k]   (w1q part)
// grid(8), block(512). Tiny (2 M-MAC); w1q is L2-resident after first block.
// ---------------------------------------------------------------------------
__global__ void qproj_kernel(const float* __restrict__ in_emb,
                             const float* __restrict__ w1,
                             const float* __restrict__ b1) {
    __shared__ float s_in[H_];
    int b = blockIdx.x;
    int k = threadIdx.x;          // 0..511
    s_in[k] = in_emb[b * H_ + k];
    __syncthreads();

    const float4* wrow = reinterpret_cast<const float4*>(w1 + (size_t)k * 1024);
    const float4* sv   = reinterpret_cast<const float4*>(s_in);
    float acc = 0.f;
#pragma unroll 8
    for (int h4 = 0; h4 < H_ / 4; h4++) {
        float4 wv = wrow[h4];
        float4 iv = sv[h4];
        acc += wv.x * iv.x + wv.y * iv.y + wv.z * iv.z + wv.w * iv.w;
    }
    g_qb[b * H_ + k] = acc + b1[k];
}

// ---------------------------------------------------------------------------
// Kernel 2: init output. Decoder part -> 0, repair part -> -1000*(1-mask).
// Main kernel then atomicAdds (mask-scaled) partials on top.
// ---------------------------------------------------------------------------
__global__ void init_out_kernel(float* __restrict__ out,
                                const float* __restrict__ mask) {
    int idx = blockIdx.x * 256 + threadIdx.x;
    if (idx >= B_ * OUTC) return;
    int b = idx / OUTC;
    int c = idx - b * OUTC;
    float v = 0.f;
    if (c >= V_) {
        float m = mask[b * T_ + (c - V_)];
        v = -1000.f * (1.f - m);
    }
    out[idx] = v;
}

// ---------------------------------------------------------------------------
// Kernel 3: fused GEMM + relu + w2-dot epilogue.
//   Row space: [0, 32000)  -> decoder_weight rows (8 outputs each, one per b)
//              [32000, 48384) -> target rows (1 output, b = row/2048)
//   C[r][n] = sum_h A[r][h] * w1t[n][h]   (NT GEMM, both K-contiguous)
//   epilogue: out += sum_{n in tile} relu(C[r][n] + qb[b][n]) * w2[n]
// grid(378, 4): 250 decoder row-tiles + 128 repair row-tiles; 4 N-tiles of 128.
// ---------------------------------------------------------------------------
__global__ __launch_bounds__(256, 2)
void fused_gemm_kernel(const float* __restrict__ tgt,
                       const float* __restrict__ mask,
                       const float* __restrict__ w1,
                       const float* __restrict__ w2,
                       const float* __restrict__ dec,
                       float* __restrict__ out) {
    __shared__ float As[BK * LDS_];
    __shared__ float Bs[BK * LDS_];
    __shared__ float qs[B_ * BN];
    __shared__ float w2s[BN];

    const int bx = blockIdx.x;
    const int n0 = blockIdx.y * BN;
    const bool isdec = (bx < V_ / BM);   // < 250

    const float* Aptr;
    int bb = 0, r0 = 0;
    if (isdec) {
        Aptr = dec + (size_t)bx * BM * H_;
    } else {
        r0 = (bx - V_ / BM) * BM;        // global repair row (0..16383)
        Aptr = tgt + (size_t)r0 * H_;
        bb = r0 / T_;                    // uniform: 128 divides 2048
    }

    const int tid = threadIdx.x;
    const int tx = tid & 15;
    const int ty = tid >> 4;

    float acc[8][8];
#pragma unroll
    for (int i = 0; i < 8; i++)
#pragma unroll
        for (int j = 0; j < 8; j++) acc[i][j] = 0.f;

    const float* Bbase = w1 + H_;        // w1t: w1[n*1024 + 512 + h]

    for (int kb = 0; kb < H_; kb += BK) {
        // ---- load A tile (128 x 16) transposed into As[k][m], +4 pad ----
#pragma unroll
        for (int t = 0; t < 2; t++) {
            int idx = tid + t * 256;       // 512 float4 total
            int row = idx >> 2;
            int k4  = idx & 3;
            float4 v = *reinterpret_cast<const float4*>(
                Aptr + (size_t)row * H_ + kb + k4 * 4);
            As[(k4 * 4 + 0) * LDS_ + row] = v.x;
            As[(k4 * 4 + 1) * LDS_ + row] = v.y;
            As[(k4 * 4 + 2) * LDS_ + row] = v.z;
            As[(k4 * 4 + 3) * LDS_ + row] = v.w;
        }
        // ---- load B tile (128 cols of w1t x 16) transposed into Bs[k][n] ----
#pragma unroll
        for (int t = 0; t < 2; t++) {
            int idx = tid + t * 256;
            int col = idx >> 2;
            int k4  = idx & 3;
            float4 v = *reinterpret_cast<const float4*>(
                Bbase + (size_t)(n0 + col) * 1024 + kb + k4 * 4);
            Bs[(k4 * 4 + 0) * LDS_ + col] = v.x;
            Bs[(k4 * 4 + 1) * LDS_ + col] = v.y;
            Bs[(k4 * 4 + 2) * LDS_ + col] = v.z;
            Bs[(k4 * 4 + 3) * LDS_ + col] = v.w;
        }
        __syncthreads();

#pragma unroll
        for (int k = 0; k < BK; k++) {
            float a[8], b[8];
            *reinterpret_cast<float4*>(&a[0]) =
                *reinterpret_cast<const float4*>(&As[k * LDS_ + ty * 4]);
            *reinterpret_cast<float4*>(&a[4]) =
                *reinterpret_cast<const float4*>(&As[k * LDS_ + 64 + ty * 4]);
            *reinterpret_cast<float4*>(&b[0]) =
                *reinterpret_cast<const float4*>(&Bs[k * LDS_ + tx * 4]);
            *reinterpret_cast<float4*>(&b[4]) =
                *reinterpret_cast<const float4*>(&Bs[k * LDS_ + 64 + tx * 4]);
#pragma unroll
            for (int i = 0; i < 8; i++)
#pragma unroll
                for (int j = 0; j < 8; j++) acc[i][j] += a[i] * b[j];
        }
        __syncthreads();
    }

    // ---- epilogue: relu(acc + qb) . w2, partial over this N-tile ----
    for (int idx = tid; idx < B_ * BN; idx += 256) {
        int b = idx >> 7;
        int c = idx & (BN - 1);
        qs[b * BN + c] = g_qb[b * H_ + n0 + c];
    }
    if (tid < BN) w2s[tid] = w2[n0 + tid];
    __syncthreads();

    int rowl[8], coll[8];
#pragma unroll
    for (int i = 0; i < 4; i++) { rowl[i] = ty * 4 + i;      rowl[i + 4] = 64 + ty * 4 + i; }
#pragma unroll
    for (int j = 0; j < 4; j++) { coll[j] = tx * 4 + j;      coll[j + 4] = 64 + tx * 4 + j; }

    float wv[8];
#pragma unroll
    for (int j = 0; j < 8; j++) wv[j] = w2s[coll[j]];

    const int nb = isdec ? B_ : 1;
    for (int bi = 0; bi < nb; bi++) {
        const int b = isdec ? bi : bb;
        float qv[8];
#pragma unroll
        for (int j = 0; j < 8; j++) qv[j] = qs[b * BN + coll[j]];
#pragma unroll
        for (int i = 0; i < 8; i++) {
            float s = 0.f;
#pragma unroll
            for (int j = 0; j < 8; j++) {
                float v = fmaxf(acc[i][j] + qv[j], 0.f);
                s += v * wv[j];
            }
            // reduce over the 16 tx lanes (stays within half-warp)
            s += __shfl_xor_sync(0xffffffffu, s, 1);
            s += __shfl_xor_sync(0xffffffffu, s, 2);
            s += __shfl_xor_sync(0xffffffffu, s, 4);
            s += __shfl_xor_sync(0xffffffffu, s, 8);
            if (tx == 0) {
                int r = rowl[i];
                if (isdec) {
                    int v = bx * BM + r;                    // vocab index
                    atomicAdd(&out[b * OUTC + v], s);
                } else {
                    int t  = r0 + r;                        // global repair row
                    int tt = t - bb * T_;                   // within-batch t
                    float m = mask[t];                      // mask[b*T_+tt]
                    atomicAdd(&out[b * OUTC + V_ + tt], m * s);
                }
            }
        }
    }
}

// ---------------------------------------------------------------------------
// launch
// inputs: 0=input_embeds 1=target_embeds 2=input_mask 3=w1 4=b1 5=w2 6=decoder_weight
// ---------------------------------------------------------------------------
extern "C" void kernel_launch(void* const* d_in, const int* in_sizes, int n_in,
                              void* d_out, int out_size) {
    const float* in_emb = (const float*)d_in[0];
    const float* tgt    = (const float*)d_in[1];
    const float* mask   = (const float*)d_in[2];
    const float* w1     = (const float*)d_in[3];
    const float* b1     = (const float*)d_in[4];
    const float* w2     = (const float*)d_in[5];
    const float* dec    = (const float*)d_in[6];
    float* out = (float*)d_out;

    qproj_kernel<<<B_, H_>>>(in_emb, w1, b1);

    int tot = B_ * OUTC;
    init_out_kernel<<<(tot + 255) / 256, 256>>>(out, mask);

    dim3 grid(NROWS / BM, H_ / BN);   // (378, 4)
    fused_gemm_kernel<<<grid, 256>>>(tgt, mask, w1, w2, dec, out);
}

// round 7
// speedup vs baseline: 2.3088x; 2.3088x over previous
#include <cuda_runtime.h>
#include <cuda_bf16.h>
#include <cstdint>

#define B_   8
#define T_   2048
#define H_   512
#define V_   32000
#define OUTC (V_ + T_)            // 34048
#define NROWS (V_ + B_ * T_)      // 48384
#define MT   (NROWS / 128)        // 378 M-tiles
#define DECT (V_ / 128)           // 250 decoder tiles
#define NST  8                    // K stages of 64

// ---------------- gmem staging (static __device__, no allocs) ----------------
__device__ float g_qb[B_ * H_];                                   // qproj + b1
__device__ __align__(16) unsigned char g_WB[NST][2][65536];       // [stage][nt>>1][(nt&1)*2+split][16KB swizzled]
__device__ __align__(16) unsigned char g_AB[MT][NST][2][16384];   // [mtile][stage][split][16KB swizzled]

// ---------------- helpers ----------------
__device__ __forceinline__ uint32_t smem_u32(const void* p) {
    uint32_t a;
    asm("{ .reg .u64 t; cvta.to.shared.u64 t, %1; cvt.u32.u64 %0, t; }" : "=r"(a) : "l"(p));
    return a;
}
#define SWZ128(o) ((o) ^ (((o) >> 3) & 0x70))

#define MBAR_INIT(a, c) \
    asm volatile("mbarrier.init.shared.b64 [%0], %1;" :: "r"(a), "r"(c) : "memory")
#define MBAR_EXPECT(a, b) \
    asm volatile("mbarrier.arrive.expect_tx.shared.b64 _, [%0], %1;" :: "r"(a), "r"(b) : "memory")
#define MBAR_WAIT(a, par) do {                                              \
    asm volatile("{\n\t.reg .pred P;\n\t"                                   \
        "WL%=:\n\t"                                                         \
        "mbarrier.try_wait.parity.acquire.cta.shared::cta.b64 P, [%0], %1, 0x989680;\n\t" \
        "@P bra.uni WD%=;\n\t"                                              \
        "bra.uni WL%=;\n\t"                                                 \
        "WD%=:\n\t}"                                                        \
        :: "r"(a), "r"(par) : "memory");                                    \
} while (0)

__device__ __forceinline__ void bulk_g2s(uint32_t dst, const void* src, uint32_t bytes, uint32_t mbar) {
    asm volatile("cp.async.bulk.shared::cta.global.mbarrier::complete_tx::bytes [%0], [%1], %2, [%3];"
        :: "r"(dst), "l"(src), "r"(bytes), "r"(mbar) : "memory");
}

#define LDSM4(r, a) \
    asm volatile("ldmatrix.sync.aligned.m8n8.x4.shared.b16 {%0,%1,%2,%3}, [%4];" \
        : "=r"((r)[0]), "=r"((r)[1]), "=r"((r)[2]), "=r"((r)[3]) : "r"(a))

#define MMA16816(c, a, b0, b1) \
    asm volatile("mma.sync.aligned.m16n8k16.row.col.f32.bf16.bf16.f32 " \
        "{%0,%1,%2,%3}, {%4,%5,%6,%7}, {%8,%9}, {%0,%1,%2,%3};" \
        : "+f"((c)[0]), "+f"((c)[1]), "+f"((c)[2]), "+f"((c)[3]) \
        : "r"((a)[0]), "r"((a)[1]), "r"((a)[2]), "r"((a)[3]), "r"(b0), "r"(b1))

// ---------------- smem layout (relative to 1KB-aligned base) ----------------
#define SM_STG   0          // 2 stages x 64KB: [Ahi|Alo|Bhi|Blo] x 16KB
#define SM_QS    131072     // 8*128 fp32 slice of qb = 4KB
#define SM_W2    135168     // 128 fp32 = 512B
#define SM_PART  135680     // 4 wn x 128 rows x 8 b fp32 = 16KB
#define SM_BAR   152064     // 2 mbarriers
#define SMEM_DYN (152064 + 16 + 1024)

// ===========================================================================
// Prep 1: qproj  g_qb[b][k] = sum_h in[b,h]*w1[k,h] + b1[k]
// ===========================================================================
__global__ void qproj_kernel(const float* __restrict__ in_emb,
                             const float* __restrict__ w1,
                             const float* __restrict__ b1) {
    __shared__ float sin_[H_];
    __shared__ float sred[256];
    int b = blockIdx.x, kg = blockIdx.y, tid = threadIdx.x;
    sin_[tid] = in_emb[b * H_ + tid];
    sin_[tid + 256] = in_emb[b * H_ + tid + 256];
    __syncthreads();
    int kq = tid & 63, q = tid >> 6;
    int k = kg * 64 + kq;
    const float4* wr = reinterpret_cast<const float4*>(w1 + (size_t)k * 1024) + q * 32;
    const float4* sv = reinterpret_cast<const float4*>(sin_) + q * 32;
    float acc = 0.f;
#pragma unroll 8
    for (int i = 0; i < 32; i++) {
        float4 w = wr[i], x = sv[i];
        acc += w.x * x.x + w.y * x.y + w.z * x.z + w.w * x.w;
    }
    sred[tid] = acc;
    __syncthreads();
    if (q == 0)
        g_qb[b * H_ + k] = sred[kq] + sred[kq + 64] + sred[kq + 128] + sred[kq + 192] + b1[k];
}

// ===========================================================================
// Prep 2: w1t -> bf16 hi/lo, SW128-swizzled 16KB chunks
// ===========================================================================
__global__ void wprep_kernel(const float* __restrict__ w1) {
    int t = blockIdx.x * 256 + threadIdx.x;      // 65536 float4s
    int n = t >> 7, j = t & 127;
    float4 v = *reinterpret_cast<const float4*>(w1 + (size_t)n * 1024 + 512 + j * 4);
    int k = j * 4, s = k >> 6, kl = k & 63;
    int nsub = n >> 7, h = nsub >> 1, p = nsub & 1, nl = n & 127;
    uint32_t sw = SWZ128((uint32_t)(nl * 128 + kl * 2));
    float x[4] = {v.x, v.y, v.z, v.w};
    __nv_bfloat16 hi[4], lo[4];
#pragma unroll
    for (int i = 0; i < 4; i++) {
        hi[i] = __float2bfloat16(x[i]);
        lo[i] = __float2bfloat16(x[i] - __bfloat162float(hi[i]));
    }
    uint2 uh, ul;
    { __nv_bfloat162 a(hi[0], hi[1]), b(hi[2], hi[3]); uh.x = *(uint32_t*)&a; uh.y = *(uint32_t*)&b; }
    { __nv_bfloat162 a(lo[0], lo[1]), b(lo[2], lo[3]); ul.x = *(uint32_t*)&a; ul.y = *(uint32_t*)&b; }
    *reinterpret_cast<uint2*>(&g_WB[s][h][(p * 2 + 0) * 16384 + sw]) = uh;
    *reinterpret_cast<uint2*>(&g_WB[s][h][(p * 2 + 1) * 16384 + sw]) = ul;
}

// ===========================================================================
// Prep 3: A rows (dec then tgt) -> bf16 hi/lo swizzled chunks
// ===========================================================================
__global__ void aprep_kernel(const float* __restrict__ dec,
                             const float* __restrict__ tgt) {
    int t = blockIdx.x * 256 + threadIdx.x;      // NROWS*128 float4s
    int r = t >> 7, j = t & 127;
    const float* row = (r < V_) ? (dec + (size_t)r * H_) : (tgt + (size_t)(r - V_) * H_);
    float4 v = reinterpret_cast<const float4*>(row)[j];
    int k = j * 4, mt = r >> 7, rl = r & 127, s = k >> 6, kl = k & 63;
    uint32_t sw = SWZ128((uint32_t)(rl * 128 + kl * 2));
    float x[4] = {v.x, v.y, v.z, v.w};
    __nv_bfloat16 hi[4], lo[4];
#pragma unroll
    for (int i = 0; i < 4; i++) {
        hi[i] = __float2bfloat16(x[i]);
        lo[i] = __float2bfloat16(x[i] - __bfloat162float(hi[i]));
    }
    uint2 uh, ul;
    { __nv_bfloat162 a(hi[0], hi[1]), b(hi[2], hi[3]); uh.x = *(uint32_t*)&a; uh.y = *(uint32_t*)&b; }
    { __nv_bfloat162 a(lo[0], lo[1]), b(lo[2], lo[3]); ul.x = *(uint32_t*)&a; ul.y = *(uint32_t*)&b; }
    *reinterpret_cast<uint2*>(&g_AB[mt][s][0][sw]) = uh;
    *reinterpret_cast<uint2*>(&g_AB[mt][s][1][sw]) = ul;
}

// ===========================================================================
// Kernel: init output (decoder -> 0, repair -> -1000*(1-mask))
// ===========================================================================
__global__ void init_out_kernel(float* __restrict__ out,
                                const float* __restrict__ mask) {
    int idx = blockIdx.x * 256 + threadIdx.x;
    if (idx >= B_ * OUTC) return;
    int b = idx / OUTC;
    int c = idx - b * OUTC;
    float v = 0.f;
    if (c >= V_) {
        float m = mask[b * T_ + (c - V_)];
        v = -1000.f * (1.f - m);
    }
    out[idx] = v;
}

// ===========================================================================
// Main: grid(4 ntiles, 378 mtiles). CTA 128x128 tile, K=512 in 8 chunks of 64,
// double-buffered cp.async.bulk, warp-level bf16 mma (3-pass hi/lo split),
// fused relu/w2 epilogue with atomicAdd partials over the 4 n-tiles.
// ===========================================================================
__global__ __launch_bounds__(256, 1)
void main_kernel(const float* __restrict__ mask,
                 const float* __restrict__ w2,
                 float* __restrict__ out) {
    extern __shared__ unsigned char smraw[];
    uint32_t sb0 = smem_u32(smraw);
    uint32_t sb = (sb0 + 1023) & ~1023u;
    unsigned char* dyn = smraw + (sb - sb0);

    const int tid = threadIdx.x;
    const int lane = tid & 31, wid = tid >> 5;
    const int wm = wid & 1, wn = wid >> 1;          // 2 x 4 warp grid (64m x 32n)
    const int nt = blockIdx.x, mtile = blockIdx.y;
    const int n0 = nt * 128;
    const bool isdec = (mtile < DECT);

    const int lrow = lane & 15, lhalf = lane >> 4;
    const uint32_t axor = (uint32_t)(lrow & 7);
    uint32_t aoff[4], boff[2];
#pragma unroll
    for (int mi = 0; mi < 4; mi++) aoff[mi] = (uint32_t)((wm * 64 + mi * 16 + lrow) * 128);
#pragma unroll
    for (int p = 0; p < 2; p++)   boff[p]  = (uint32_t)((wn * 32 + p * 16 + lrow) * 128);

    const uint32_t bar = sb + SM_BAR;
    const unsigned char* abase = &g_AB[mtile][0][0][0];
    const unsigned char* bbase = &g_WB[0][nt >> 1][(nt & 1) * 2 * 16384];

    if (tid == 0) {
        MBAR_INIT(bar + 0, 1);
        MBAR_INIT(bar + 8, 1);
#pragma unroll
        for (int c = 0; c < 2; c++) {
            uint32_t stg = sb + SM_STG + c * 65536;
            MBAR_EXPECT(bar + c * 8, 65536);
            bulk_g2s(stg,         abase + (size_t)c * 32768, 32768, bar + c * 8);
            bulk_g2s(stg + 32768, &g_WB[c][nt >> 1][(nt & 1) * 2 * 16384], 32768, bar + c * 8);
        }
    }
    (void)bbase;

    // stage qb slice + w2 slice (overlaps with first TMA)
    float* qsp = (float*)(dyn + SM_QS);
    float* w2p = (float*)(dyn + SM_W2);
    for (int i = tid; i < B_ * 128; i += 256) qsp[i] = g_qb[(i >> 7) * H_ + n0 + (i & 127)];
    if (tid < 128) w2p[tid] = w2[n0 + tid];
    __syncthreads();   // mbarrier inits visible to all waiters

    float acc[4][4][4];
#pragma unroll
    for (int mi = 0; mi < 4; mi++)
#pragma unroll
        for (int ni = 0; ni < 4; ni++)
#pragma unroll
            for (int x = 0; x < 4; x++) acc[mi][ni][x] = 0.f;

    for (int c = 0; c < NST; c++) {
        const int buf = c & 1;
        const uint32_t stg = sb + SM_STG + buf * 65536;
        MBAR_WAIT(bar + buf * 8, (c >> 1) & 1);

        const uint32_t sAhi = stg, sAlo = stg + 16384;
        const uint32_t sBhi = stg + 32768, sBlo = stg + 49152;

#pragma unroll
        for (int kk = 0; kk < 4; kk++) {
            const uint32_t jsw = (((uint32_t)(kk * 2 + lhalf)) ^ axor) << 4;

            uint32_t Ah[4][4], Bh[2][4], Bl[2][4];
#pragma unroll
            for (int mi = 0; mi < 4; mi++) LDSM4(Ah[mi], sAhi + aoff[mi] + jsw);
#pragma unroll
            for (int p = 0; p < 2; p++) {
                LDSM4(Bh[p], sBhi + boff[p] + jsw);
                LDSM4(Bl[p], sBlo + boff[p] + jsw);
            }
            // pass 1: Ahi * Bhi
#pragma unroll
            for (int mi = 0; mi < 4; mi++)
#pragma unroll
                for (int ni = 0; ni < 4; ni++)
                    MMA16816(acc[mi][ni], Ah[mi], Bh[ni >> 1][ni & 1], Bh[ni >> 1][(ni & 1) + 2]);
            // pass 2: Ahi * Blo
#pragma unroll
            for (int mi = 0; mi < 4; mi++)
#pragma unroll
                for (int ni = 0; ni < 4; ni++)
                    MMA16816(acc[mi][ni], Ah[mi], Bl[ni >> 1][ni & 1], Bl[ni >> 1][(ni & 1) + 2]);
            // pass 3: Alo * Bhi
            uint32_t Al[4][4];
#pragma unroll
            for (int mi = 0; mi < 4; mi++) LDSM4(Al[mi], sAlo + aoff[mi] + jsw);
#pragma unroll
            for (int mi = 0; mi < 4; mi++)
#pragma unroll
                for (int ni = 0; ni < 4; ni++)
                    MMA16816(acc[mi][ni], Al[mi], Bh[ni >> 1][ni & 1], Bh[ni >> 1][(ni & 1) + 2]);
        }
        __syncthreads();   // all warps done with this buffer
        int nc = c + 2;
        if (tid == 0 && nc < NST) {
            uint32_t nstg = sb + SM_STG + buf * 65536;
            MBAR_EXPECT(bar + buf * 8, 65536);
            bulk_g2s(nstg,         abase + (size_t)nc * 32768, 32768, bar + buf * 8);
            bulk_g2s(nstg + 32768, &g_WB[nc][nt >> 1][(nt & 1) * 2 * 16384], 32768, bar + buf * 8);
        }
    }

    // ---- epilogue: s(row) = sum_n relu(acc + qb[b][n]) * w2[n] ----
    const int tq = lane >> 2, tr = lane & 3;
    float* part = (float*)(dyn + SM_PART);   // [wn][row(128)][b(8)]

    float w2v[8];
#pragma unroll
    for (int ni = 0; ni < 4; ni++)
#pragma unroll
        for (int j = 0; j < 2; j++)
            w2v[ni * 2 + j] = w2p[wn * 32 + ni * 8 + tr * 2 + j];

    if (isdec) {
#pragma unroll
        for (int g = 0; g < 8; g++) {
            const int mi = g >> 1, hf = g & 1;
            const int rloc = wm * 64 + mi * 16 + hf * 8 + tq;
#pragma unroll
            for (int b = 0; b < B_; b++) {
                float s = 0.f;
#pragma unroll
                for (int ni = 0; ni < 4; ni++)
#pragma unroll
                    for (int j = 0; j < 2; j++) {
                        float v = acc[mi][ni][hf * 2 + j] +
                                  qsp[b * 128 + wn * 32 + ni * 8 + tr * 2 + j];
                        v = fmaxf(v, 0.f);
                        s = fmaf(v, w2v[ni * 2 + j], s);
                    }
                s += __shfl_xor_sync(0xffffffffu, s, 1);
                s += __shfl_xor_sync(0xffffffffu, s, 2);
                if (tr == 0) part[wn * 1024 + rloc * 8 + b] = s;
            }
        }
    } else {
        const int r0g = (mtile - DECT) * 128;
        const int bloc = r0g >> 11;              // uniform per tile (128 | 2048)
#pragma unroll
        for (int g = 0; g < 8; g++) {
            const int mi = g >> 1, hf = g & 1;
            const int rloc = wm * 64 + mi * 16 + hf * 8 + tq;
            float s = 0.f;
#pragma unroll
            for (int ni = 0; ni < 4; ni++)
#pragma unroll
                for (int j = 0; j < 2; j++) {
                    float v = acc[mi][ni][hf * 2 + j] +
                              qsp[bloc * 128 + wn * 32 + ni * 8 + tr * 2 + j];
                    v = fmaxf(v, 0.f);
                    s = fmaf(v, w2v[ni * 2 + j], s);
                }
            s += __shfl_xor_sync(0xffffffffu, s, 1);
            s += __shfl_xor_sync(0xffffffffu, s, 2);
            if (tr == 0) part[wn * 1024 + rloc * 8] = s;
        }
    }
    __syncthreads();

    if (isdec) {
        for (int idx = tid; idx < 1024; idx += 256) {
            int row = idx >> 3, b = idx & 7;
            float t = part[idx] + part[1024 + idx] + part[2048 + idx] + part[3072 + idx];
            atomicAdd(&out[(size_t)b * OUTC + mtile * 128 + row], t);
        }
    } else {
        if (tid < 128) {
            int tg = (mtile - DECT) * 128 + tid;
            int bloc = tg >> 11, tt = tg & (T_ - 1);
            float t = part[tid * 8] + part[1024 + tid * 8] +
                      part[2048 + tid * 8] + part[3072 + tid * 8];
            float m = mask[tg];
            atomicAdd(&out[(size_t)bloc * OUTC + V_ + tt], m * t);
        }
    }
}

// ---------------------------------------------------------------------------
// launch: 0=input_embeds 1=target_embeds 2=input_mask 3=w1 4=b1 5=w2 6=decoder_weight
// ---------------------------------------------------------------------------
extern "C" void kernel_launch(void* const* d_in, const int* in_sizes, int n_in,
                              void* d_out, int out_size) {
    const float* in_emb = (const float*)d_in[0];
    const float* tgt    = (const float*)d_in[1];
    const float* mask   = (const float*)d_in[2];
    const float* w1     = (const float*)d_in[3];
    const float* b1     = (const float*)d_in[4];
    const float* w2     = (const float*)d_in[5];
    const float* dec    = (const float*)d_in[6];
    float* out = (float*)d_out;

    static int smem_set = 0;
    if (!smem_set) {
        cudaFuncSetAttribute(main_kernel, cudaFuncAttributeMaxDynamicSharedMemorySize, SMEM_DYN);
        smem_set = 1;
    }

    qproj_kernel<<<dim3(B_, 8), 256>>>(in_emb, w1, b1);
    wprep_kernel<<<256, 256>>>(w1);
    aprep_kernel<<<(NROWS * 128) / 256, 256>>>(dec, tgt);
    int tot = B_ * OUTC;
    init_out_kernel<<<(tot + 255) / 256, 256>>>(out, mask);
    main_kernel<<<dim3(4, MT), 256, SMEM_DYN>>>(mask, w2, out);
}

// round 8
// speedup vs baseline: 2.7850x; 1.2063x over previous
#include <cuda_runtime.h>
#include <cuda_fp16.h>
#include <cstdint>

#define B_   8
#define T_   2048
#define H_   512
#define V_   32000
#define OUTC (V_ + T_)            // 34048
#define NROWS (V_ + B_ * T_)      // 48384
#define MT   (NROWS / 128)        // 378
#define DECT (V_ / 128)           // 250
#define NST  8                    // K chunks of 64

// ---------------- gmem staging (static, no allocs) ----------------
__device__ float g_qb[B_ * H_];                                 // qproj + b1
__device__ __align__(16) unsigned char g_A16[MT][NST][16384];   // 47.25 MB fp16 swizzled
__device__ __align__(16) unsigned char g_B16[4][NST][16384];    // 512 KB fp16 swizzled

// ---------------- helpers ----------------
__device__ __forceinline__ uint32_t smem_u32(const void* p) {
    uint32_t a;
    asm("{ .reg .u64 t; cvta.to.shared.u64 t, %1; cvt.u32.u64 %0, t; }" : "=r"(a) : "l"(p));
    return a;
}
#define SWZ128(o) ((o) ^ (((o) >> 3) & 0x70))

#define MBAR_INIT(a, c) \
    asm volatile("mbarrier.init.shared.b64 [%0], %1;" :: "r"(a), "r"(c) : "memory")
#define MBAR_EXPECT(a, b) \
    asm volatile("mbarrier.arrive.expect_tx.shared.b64 _, [%0], %1;" :: "r"(a), "r"(b) : "memory")
#define MBAR_WAIT(a, par) do {                                              \
    asm volatile("{\n\t.reg .pred P;\n\t"                                   \
        "WL%=:\n\t"                                                         \
        "mbarrier.try_wait.parity.acquire.cta.shared::cta.b64 P, [%0], %1, 0x989680;\n\t" \
        "@P bra.uni WD%=;\n\t"                                              \
        "bra.uni WL%=;\n\t"                                                 \
        "WD%=:\n\t}"                                                        \
        :: "r"(a), "r"(par) : "memory");                                    \
} while (0)

__device__ __forceinline__ void bulk_g2s(uint32_t dst, const void* src, uint32_t bytes, uint32_t mbar) {
    asm volatile("cp.async.bulk.shared::cta.global.mbarrier::complete_tx::bytes [%0], [%1], %2, [%3];"
        :: "r"(dst), "l"(src), "r"(bytes), "r"(mbar) : "memory");
}

#define LDSM4(r, a) \
    asm volatile("ldmatrix.sync.aligned.m8n8.x4.shared.b16 {%0,%1,%2,%3}, [%4];" \
        : "=r"((r)[0]), "=r"((r)[1]), "=r"((r)[2]), "=r"((r)[3]) : "r"(a))

#define MMA16816(c, a, b0, b1) \
    asm volatile("mma.sync.aligned.m16n8k16.row.col.f32.f16.f16.f32 " \
        "{%0,%1,%2,%3}, {%4,%5,%6,%7}, {%8,%9}, {%0,%1,%2,%3};" \
        : "+f"((c)[0]), "+f"((c)[1]), "+f"((c)[2]), "+f"((c)[3]) \
        : "r"((a)[0]), "r"((a)[1]), "r"((a)[2]), "r"((a)[3]), "r"(b0), "r"(b1))

// ---------------- main-kernel smem layout (1KB-aligned base) ----------------
#define SM_A     0          // 8 chunks x 16KB = 128KB (full A tile, fp16)
#define SM_B     131072     // 4-slot ring x 16KB = 64KB
#define SM_QB    196608     // 8 x 512 fp32 = 16KB
#define SM_W2    212992     // 512 fp32 = 2KB
#define SM_PART  215040     // 128 rows x 8 b fp32 = 4KB
#define SM_BAR   219136     // A bars (8x8B) @ +0, B bars (4x8B) @ +64
#define SMEM_DYN (219264 + 1024)

__device__ __forceinline__ uint2 pack4h(float a, float b, float c, float d) {
    __half2 p01(__float2half_rn(a), __float2half_rn(b));
    __half2 p23(__float2half_rn(c), __float2half_rn(d));
    uint2 u;
    u.x = *reinterpret_cast<uint32_t*>(&p01);
    u.y = *reinterpret_cast<uint32_t*>(&p23);
    return u;
}

// ===========================================================================
// Fused prep: [0,24192) aprep | [24192,24448) wprep | [24448,24512) qproj
// ===========================================================================
#define APREP_BLKS 24192
#define WPREP_BLKS 256
#define QPROJ_BLKS 64

__global__ void prep_kernel(const float* __restrict__ in_emb,
                            const float* __restrict__ w1,
                            const float* __restrict__ b1,
                            const float* __restrict__ dec,
                            const float* __restrict__ tgt) {
    __shared__ float sin_[H_];
    __shared__ float sred[256];
    const int bid = blockIdx.x, tid = threadIdx.x;

    if (bid < APREP_BLKS) {
        // A rows (dec then tgt) -> fp16 swizzled chunks
        int t = bid * 256 + tid;                 // NROWS*128 threads
        int r = t >> 7, j = t & 127;
        const float* row = (r < V_) ? (dec + (size_t)r * H_) : (tgt + (size_t)(r - V_) * H_);
        float4 v = reinterpret_cast<const float4*>(row)[j];
        int k = j * 4, mt = r >> 7, rl = r & 127, s = k >> 6, kl = k & 63;
        uint32_t sw = SWZ128((uint32_t)(rl * 128 + kl * 2));
        *reinterpret_cast<uint2*>(&g_A16[mt][s][sw]) = pack4h(v.x, v.y, v.z, v.w);
    } else if (bid < APREP_BLKS + WPREP_BLKS) {
        // w1t -> fp16 swizzled chunks
        int t = (bid - APREP_BLKS) * 256 + tid;  // 512*128 threads
        int n = t >> 7, j = t & 127;
        float4 v = *reinterpret_cast<const float4*>(w1 + (size_t)n * 1024 + 512 + j * 4);
        int k = j * 4, nt = n >> 7, nl = n & 127, s = k >> 6, kl = k & 63;
        uint32_t sw = SWZ128((uint32_t)(nl * 128 + kl * 2));
        *reinterpret_cast<uint2*>(&g_B16[nt][s][sw]) = pack4h(v.x, v.y, v.z, v.w);
    } else {
        // qproj: g_qb[b][k] = sum_h in[b,h]*w1[k,h] + b1[k]
        int q = bid - (APREP_BLKS + WPREP_BLKS);
        int b = q >> 3, kg = q & 7;
        sin_[tid] = in_emb[b * H_ + tid];
        sin_[tid + 256] = in_emb[b * H_ + tid + 256];
        __syncthreads();
        int kq = tid & 63, qq = tid >> 6;
        int k = kg * 64 + kq;
        const float4* wr = reinterpret_cast<const float4*>(w1 + (size_t)k * 1024) + qq * 32;
        const float4* sv = reinterpret_cast<const float4*>(sin_) + qq * 32;
        float acc = 0.f;
#pragma unroll 8
        for (int i = 0; i < 32; i++) {
            float4 w = wr[i], x = sv[i];
            acc += w.x * x.x + w.y * x.y + w.z * x.z + w.w * x.w;
        }
        sred[tid] = acc;
        __syncthreads();
        if (qq == 0)
            g_qb[b * H_ + k] = sred[kq] + sred[kq + 64] + sred[kq + 128] + sred[kq + 192] + b1[k];
    }
}

// ===========================================================================
// Main: one CTA per 128-row M-tile. Full A (128x512 fp16) resident in smem.
// Loop 4 n-slices of 128; B streamed through 4-deep 16KB ring; single-pass
// fp16 mma; epilogue reduces over N in-CTA (smem atomics); outputs written
// exactly once with mask fused.
// ===========================================================================
__global__ __launch_bounds__(256, 1)
void main_kernel(const float* __restrict__ mask,
                 const float* __restrict__ w2,
                 float* __restrict__ out) {
    extern __shared__ unsigned char smraw[];
    uint32_t sb0 = smem_u32(smraw);
    uint32_t sb = (sb0 + 1023) & ~1023u;
    unsigned char* dyn = smraw + (sb - sb0);

    const int tid = threadIdx.x;
    const int lane = tid & 31, wid = tid >> 5;
    const int wm = wid & 1, wn = wid >> 1;           // 2(m) x 4(n) warp grid
    const int mtile = blockIdx.x;
    const bool isdec = (mtile < DECT);

    const int lrow = lane & 15, lhalf = lane >> 4;
    const uint32_t axor = (uint32_t)(lrow & 7);
    uint32_t aoff[4], boffb[2];
#pragma unroll
    for (int mi = 0; mi < 4; mi++) aoff[mi] = (uint32_t)((wm * 64 + mi * 16 + lrow) * 128);
#pragma unroll
    for (int p = 0; p < 2; p++)   boffb[p] = (uint32_t)((wn * 32 + p * 16 + lrow) * 128);

    const uint32_t abar = sb + SM_BAR;
    const uint32_t bbar = sb + SM_BAR + 64;
    const unsigned char* aptr = &g_A16[mtile][0][0];
    const unsigned char* bptr = &g_B16[0][0][0];

    float* qsp = (float*)(dyn + SM_QB);
    float* w2p = (float*)(dyn + SM_W2);
    float* part = (float*)(dyn + SM_PART);

    if (tid == 0) {
#pragma unroll
        for (int s = 0; s < NST; s++) MBAR_INIT(abar + s * 8, 1);
#pragma unroll
        for (int g = 0; g < 4; g++) MBAR_INIT(bbar + g * 8, 1);
#pragma unroll
        for (int s = 0; s < NST; s++) {
            MBAR_EXPECT(abar + s * 8, 16384);
            bulk_g2s(sb + SM_A + s * 16384, aptr + (size_t)s * 16384, 16384, abar + s * 8);
        }
#pragma unroll
        for (int g = 0; g < 4; g++) {
            MBAR_EXPECT(bbar + g * 8, 16384);
            bulk_g2s(sb + SM_B + g * 16384, bptr + (size_t)g * 16384, 16384, bbar + g * 8);
        }
    }
    // stage qb + w2 + zero partials (overlaps with copies)
    for (int i = tid; i < B_ * H_; i += 256) qsp[i] = g_qb[i];
    for (int i = tid; i < H_; i += 256) w2p[i] = w2[i];
    for (int i = tid; i < 128 * B_; i += 256) part[i] = 0.f;
    __syncthreads();   // bars initialized + smem staged before any wait

    const int tq = lane >> 2, tr = lane & 3;

    for (int nt = 0; nt < 4; nt++) {
        float acc[4][4][4];
#pragma unroll
        for (int mi = 0; mi < 4; mi++)
#pragma unroll
            for (int ni = 0; ni < 4; ni++)
#pragma unroll
                for (int x = 0; x < 4; x++) acc[mi][ni][x] = 0.f;

        for (int s = 0; s < NST; s++) {
            const int g = nt * NST + s;
            const int slot = g & 3, par = (g >> 2) & 1;
            if (nt == 0) MBAR_WAIT(abar + s * 8, 0);
            MBAR_WAIT(bbar + slot * 8, par);

            const uint32_t sA = sb + SM_A + s * 16384;
            const uint32_t sB = sb + SM_B + slot * 16384;
#pragma unroll
            for (int kk = 0; kk < 4; kk++) {
                const uint32_t jsw = (((uint32_t)(kk * 2 + lhalf)) ^ axor) << 4;
                uint32_t Af[4][4], Bf[2][4];
#pragma unroll
                for (int mi = 0; mi < 4; mi++) LDSM4(Af[mi], sA + aoff[mi] + jsw);
#pragma unroll
                for (int p = 0; p < 2; p++) LDSM4(Bf[p], sB + boffb[p] + jsw);
#pragma unroll
                for (int mi = 0; mi < 4; mi++)
#pragma unroll
                    for (int ni = 0; ni < 4; ni++)
                        MMA16816(acc[mi][ni], Af[mi], Bf[ni >> 1][ni & 1], Bf[ni >> 1][(ni & 1) + 2]);
            }
            __syncthreads();   // all warps done with this B slot
            const int ng = g + 4;
            if (tid == 0 && ng < 32) {
                MBAR_EXPECT(bbar + slot * 8, 16384);
                bulk_g2s(sb + SM_B + slot * 16384, bptr + (size_t)ng * 16384, 16384,
                         bbar + slot * 8);
            }
        }

        // ---- epilogue for this n-slice: relu(acc + qb) . w2 -> smem partials ----
        const int nbase = nt * 128 + wn * 32;
        float w2v[8];
#pragma unroll
        for (int ni = 0; ni < 4; ni++)
#pragma unroll
            for (int j = 0; j < 2; j++)
                w2v[ni * 2 + j] = w2p[nbase + ni * 8 + tr * 2 + j];

        if (isdec) {
#pragma unroll
            for (int gidx = 0; gidx < 8; gidx++) {
                const int mi = gidx >> 1, hf = gidx & 1;
                const int rloc = wm * 64 + mi * 16 + hf * 8 + tq;
#pragma unroll
                for (int b = 0; b < B_; b++) {
                    const float* qrow = &qsp[b * H_ + nbase];
                    float s = 0.f;
#pragma unroll
                    for (int ni = 0; ni < 4; ni++)
#pragma unroll
                        for (int j = 0; j < 2; j++) {
                            float v = acc[mi][ni][hf * 2 + j] + qrow[ni * 8 + tr * 2 + j];
                            v = fmaxf(v, 0.f);
                            s = fmaf(v, w2v[ni * 2 + j], s);
                        }
                    s += __shfl_xor_sync(0xffffffffu, s, 1);
                    s += __shfl_xor_sync(0xffffffffu, s, 2);
                    if (tr == 0) atomicAdd(&part[rloc * 8 + b], s);
                }
            }
        } else {
            const int bloc = ((mtile - DECT) * 128) >> 11;   // uniform per tile
            const float* qrow = &qsp[bloc * H_ + nbase];
#pragma unroll
            for (int gidx = 0; gidx < 8; gidx++) {
                const int mi = gidx >> 1, hf = gidx & 1;
                const int rloc = wm * 64 + mi * 16 + hf * 8 + tq;
                float s = 0.f;
#pragma unroll
                for (int ni = 0; ni < 4; ni++)
#pragma unroll
                    for (int j = 0; j < 2; j++) {
                        float v = acc[mi][ni][hf * 2 + j] + qrow[ni * 8 + tr * 2 + j];
                        v = fmaxf(v, 0.f);
                        s = fmaf(v, w2v[ni * 2 + j], s);
                    }
                s += __shfl_xor_sync(0xffffffffu, s, 1);
                s += __shfl_xor_sync(0xffffffffu, s, 2);
                if (tr == 0) atomicAdd(&part[rloc * 8], s);
            }
        }
    }
    __syncthreads();

    // ---- final write (each output element exactly once; mask fused) ----
    if (isdec) {
        for (int idx = tid; idx < 128 * B_; idx += 256) {
            int row = idx >> 3, b = idx & 7;
            out[(size_t)b * OUTC + mtile * 128 + row] = part[idx];
        }
    } else {
        if (tid < 128) {
            int tg = (mtile - DECT) * 128 + tid;
            int bloc = tg >> 11, tt = tg & (T_ - 1);
            float m = mask[tg];
            out[(size_t)bloc * OUTC + V_ + tt] = m * part[tid * 8] - 1000.f * (1.f - m);
        }
    }
}

// ---------------------------------------------------------------------------
// launch: 0=input_embeds 1=target_embeds 2=input_mask 3=w1 4=b1 5=w2 6=decoder_weight
// ---------------------------------------------------------------------------
extern "C" void kernel_launch(void* const* d_in, const int* in_sizes, int n_in,
                              void* d_out, int out_size) {
    const float* in_emb = (const float*)d_in[0];
    const float* tgt    = (const float*)d_in[1];
    const float* mask   = (const float*)d_in[2];
    const float* w1     = (const float*)d_in[3];
    const float* b1     = (const float*)d_in[4];
    const float* w2     = (const float*)d_in[5];
    const float* dec    = (const float*)d_in[6];
    float* out = (float*)d_out;

    static int smem_set = 0;
    if (!smem_set) {
        cudaFuncSetAttribute(main_kernel, cudaFuncAttributeMaxDynamicSharedMemorySize, SMEM_DYN);
        smem_set = 1;
    }

    prep_kernel<<<APREP_BLKS + WPREP_BLKS + QPROJ_BLKS, 256>>>(in_emb, w1, b1, dec, tgt);
    main_kernel<<<MT, 256, SMEM_DYN>>>(mask, w2, out);
}

// round 10
// speedup vs baseline: 3.5243x; 1.2654x over previous
#include <cuda_runtime.h>
#include <cuda_fp16.h>
#include <cstdint>

#define B_   8
#define T_   2048
#define H_   512
#define V_   32000
#define OUTC (V_ + T_)            // 34048
#define NROWS (V_ + B_ * T_)      // 48384
#define MT   (NROWS / 128)        // 378
#define DECT (V_ / 128)           // 250
#define NST  8                    // K chunks of 64

// ---------------- gmem staging (static, no allocs) ----------------
__device__ float g_qb[B_ * H_];                                 // qproj + b1
__device__ __align__(16) unsigned char g_A16[MT][NST][16384];   // 47.25 MB fp16 swizzled
__device__ __align__(16) unsigned char g_B16[4][NST][16384];    // 512 KB fp16 swizzled

// ---------------- helpers ----------------
__device__ __forceinline__ uint32_t smem_u32(const void* p) {
    uint32_t a;
    asm("{ .reg .u64 t; cvta.to.shared.u64 t, %1; cvt.u32.u64 %0, t; }" : "=r"(a) : "l"(p));
    return a;
}
#define SWZ128(o) ((o) ^ (((o) >> 3) & 0x70))

#define MBAR_INIT(a, c) \
    asm volatile("mbarrier.init.shared.b64 [%0], %1;" :: "r"(a), "r"(c) : "memory")
#define MBAR_EXPECT(a, b) \
    asm volatile("mbarrier.arrive.expect_tx.shared.b64 _, [%0], %1;" :: "r"(a), "r"(b) : "memory")
#define MBAR_WAIT(a, par) do {                                              \
    asm volatile("{\n\t.reg .pred P;\n\t"                                   \
        "WL%=:\n\t"                                                         \
        "mbarrier.try_wait.parity.acquire.cta.shared::cta.b64 P, [%0], %1, 0x989680;\n\t" \
        "@P bra.uni WD%=;\n\t"                                              \
        "bra.uni WL%=;\n\t"                                                 \
        "WD%=:\n\t}"                                                        \
        :: "r"(a), "r"(par) : "memory");                                    \
} while (0)

__device__ __forceinline__ void bulk_g2s(uint32_t dst, const void* src, uint32_t bytes, uint32_t mbar) {
    asm volatile("cp.async.bulk.shared::cta.global.mbarrier::complete_tx::bytes [%0], [%1], %2, [%3];"
        :: "r"(dst), "l"(src), "r"(bytes), "r"(mbar) : "memory");
}

#define LDSM4(r, a) \
    asm volatile("ldmatrix.sync.aligned.m8n8.x4.shared.b16 {%0,%1,%2,%3}, [%4];" \
        : "=r"((r)[0]), "=r"((r)[1]), "=r"((r)[2]), "=r"((r)[3]) : "r"(a))

#define MMA16816(c, a, b0, b1) \
    asm volatile("mma.sync.aligned.m16n8k16.row.col.f32.f16.f16.f32 " \
        "{%0,%1,%2,%3}, {%4,%5,%6,%7}, {%8,%9}, {%0,%1,%2,%3};" \
        : "+f"((c)[0]), "+f"((c)[1]), "+f"((c)[2]), "+f"((c)[3]) \
        : "r"((a)[0]), "r"((a)[1]), "r"((a)[2]), "r"((a)[3]), "r"(b0), "r"(b1))

// ---------------- main-kernel smem layout (1KB-aligned base) ----------------
#define SM_A     0          // 8 chunks x 16KB = 128KB (full A tile, fp16)
#define SM_B     131072     // 4-slot ring x 16KB = 64KB
#define SM_QB    196608     // 8 x 512 fp32 = 16KB
#define SM_W2    212992     // 512 fp32 = 2KB
#define SM_PART  215040     // 128 rows x 8 b fp32 = 4KB
#define SM_BAR   219136     // A bars (8x8B) @ +0, B bars (4x8B) @ +64
#define SMEM_DYN (219264 + 1024)

__device__ __forceinline__ uint2 pack4h(float a, float b, float c, float d) {
    __half2 p01(__float2half_rn(a), __float2half_rn(b));
    __half2 p23(__float2half_rn(c), __float2half_rn(d));
    uint2 u;
    u.x = *reinterpret_cast<uint32_t*>(&p01);
    u.y = *reinterpret_cast<uint32_t*>(&p23);
    return u;
}

// ===========================================================================
// Fused prep: [0,6048) aprep (8 rows/blk, MLP=4) | [6048,6112) wprep | [6112,6176) qproj
// ===========================================================================
#define APREP_BLKS 6048
#define WPREP_BLKS 64
#define QPROJ_BLKS 64

__global__ void prep_kernel(const float* __restrict__ in_emb,
                            const float* __restrict__ w1,
                            const float* __restrict__ b1,
                            const float* __restrict__ dec,
                            const float* __restrict__ tgt) {
    __shared__ float sin_[H_];
    __shared__ float sred[256];
    const int bid = blockIdx.x, tid = threadIdx.x;

    if (bid < APREP_BLKS) {
        // A rows (dec then tgt) -> fp16 swizzled chunks; 8 rows/block, 4 f4/thread
        int r = bid * 8 + (tid >> 5);
        int j0 = tid & 31;
        const float* row = (r < V_) ? (dec + (size_t)r * H_) : (tgt + (size_t)(r - V_) * H_);
        int mt = r >> 7, rl = r & 127;
        float4 v[4];
#pragma unroll
        for (int u = 0; u < 4; u++)
            v[u] = reinterpret_cast<const float4*>(row)[j0 + u * 32];
#pragma unroll
        for (int u = 0; u < 4; u++) {
            int j = j0 + u * 32;
            int s = j >> 4, kl = (j * 4) & 63;
            uint32_t sw = SWZ128((uint32_t)(rl * 128 + kl * 2));
            *reinterpret_cast<uint2*>(&g_A16[mt][s][sw]) = pack4h(v[u].x, v[u].y, v[u].z, v[u].w);
        }
    } else if (bid < APREP_BLKS + WPREP_BLKS) {
        // w1t -> fp16 swizzled chunks; 8 n-rows/block, 4 f4/thread
        int n = (bid - APREP_BLKS) * 8 + (tid >> 5);
        int j0 = tid & 31;
        const float* row = w1 + (size_t)n * 1024 + 512;
        int nt = n >> 7, nl = n & 127;
        float4 v[4];
#pragma unroll
        for (int u = 0; u < 4; u++)
            v[u] = reinterpret_cast<const float4*>(row)[j0 + u * 32];
#pragma unroll
        for (int u = 0; u < 4; u++) {
            int j = j0 + u * 32;
            int s = j >> 4, kl = (j * 4) & 63;
            uint32_t sw = SWZ128((uint32_t)(nl * 128 + kl * 2));
            *reinterpret_cast<uint2*>(&g_B16[nt][s][sw]) = pack4h(v[u].x, v[u].y, v[u].z, v[u].w);
        }
    } else {
        // qproj: g_qb[b][k] = sum_h in[b,h]*w1[k,h] + b1[k]
        int q = bid - (APREP_BLKS + WPREP_BLKS);
        int b = q >> 3, kg = q & 7;
        sin_[tid] = in_emb[b * H_ + tid];
        sin_[tid + 256] = in_emb[b * H_ + tid + 256];
        __syncthreads();
        int kq = tid & 63, qq = tid >> 6;
        int k = kg * 64 + kq;
        const float4* wr = reinterpret_cast<const float4*>(w1 + (size_t)k * 1024) + qq * 32;
        const float4* sv = reinterpret_cast<const float4*>(sin_) + qq * 32;
        float acc = 0.f;
#pragma unroll 8
        for (int i = 0; i < 32; i++) {
            float4 w = wr[i], x = sv[i];
            acc += w.x * x.x + w.y * x.y + w.z * x.z + w.w * x.w;
        }
        sred[tid] = acc;
        __syncthreads();
        if (qq == 0)
            g_qb[b * H_ + k] = sred[kq] + sred[kq + 64] + sred[kq + 128] + sred[kq + 192] + b1[k];
    }
}

// ===========================================================================
// Main: one CTA (512 threads, 16 warps) per 128-row M-tile. Full A resident.
// 4 n-slices of 128; warp grid 4(m) x 4(n), warp tile 32x32; B via 4-slot ring.
// Epilogue reduces over N in-CTA (smem atomics); outputs written exactly once.
// ===========================================================================
__global__ __launch_bounds__(512, 1)
void main_kernel(const float* __restrict__ mask,
                 const float* __restrict__ w2,
                 float* __restrict__ out) {
    extern __shared__ unsigned char smraw[];
    uint32_t sb0 = smem_u32(smraw);
    uint32_t sb = (sb0 + 1023) & ~1023u;
    unsigned char* dyn = smraw + (sb - sb0);

    const int tid = threadIdx.x;
    const int lane = tid & 31, wid = tid >> 5;
    const int wm = wid & 3, wn = wid >> 2;           // 4(m) x 4(n) warp grid
    const int mtile = blockIdx.x;
    const bool isdec = (mtile < DECT);

    const int lrow = lane & 15, lhalf = lane >> 4;
    const uint32_t axor = (uint32_t)(lrow & 7);
    uint32_t aoff[2], boffb[2];
#pragma unroll
    for (int mi = 0; mi < 2; mi++) aoff[mi] = (uint32_t)((wm * 32 + mi * 16 + lrow) * 128);
#pragma unroll
    for (int p = 0; p < 2; p++)   boffb[p] = (uint32_t)((wn * 32 + p * 16 + lrow) * 128);

    const uint32_t abar = sb + SM_BAR;
    const uint32_t bbar = sb + SM_BAR + 64;
    const unsigned char* aptr = &g_A16[mtile][0][0];
    const unsigned char* bptr = &g_B16[0][0][0];

    float* qsp = (float*)(dyn + SM_QB);
    float* w2p = (float*)(dyn + SM_W2);
    float* part = (float*)(dyn + SM_PART);

    if (tid == 0) {
#pragma unroll
        for (int s = 0; s < NST; s++) MBAR_INIT(abar + s * 8, 1);
#pragma unroll
        for (int g = 0; g < 4; g++) MBAR_INIT(bbar + g * 8, 1);
#pragma unroll
        for (int s = 0; s < NST; s++) {
            MBAR_EXPECT(abar + s * 8, 16384);
            bulk_g2s(sb + SM_A + s * 16384, aptr + (size_t)s * 16384, 16384, abar + s * 8);
        }
#pragma unroll
        for (int g = 0; g < 4; g++) {
            MBAR_EXPECT(bbar + g * 8, 16384);
            bulk_g2s(sb + SM_B + g * 16384, bptr + (size_t)g * 16384, 16384, bbar + g * 8);
        }
    }
    // stage qb + w2 + zero partials (overlaps with copies)
    for (int i = tid; i < B_ * H_; i += 512) qsp[i] = g_qb[i];
    if (tid < H_) w2p[tid] = w2[tid];
    for (int i = tid; i < 128 * B_; i += 512) part[i] = 0.f;
    __syncthreads();   // bars initialized + smem staged before any wait

    const int tq = lane >> 2, tr = lane & 3;

    for (int nt = 0; nt < 4; nt++) {
        float acc[2][4][4];
#pragma unroll
        for (int mi = 0; mi < 2; mi++)
#pragma unroll
            for (int ni = 0; ni < 4; ni++)
#pragma unroll
                for (int x = 0; x < 4; x++) acc[mi][ni][x] = 0.f;

        for (int s = 0; s < NST; s++) {
            const int g = nt * NST + s;
            const int slot = g & 3, par = (g >> 2) & 1;
            if (nt == 0) MBAR_WAIT(abar + s * 8, 0);
            MBAR_WAIT(bbar + slot * 8, par);

            const uint32_t sA = sb + SM_A + s * 16384;
            const uint32_t sB = sb + SM_B + slot * 16384;
#pragma unroll
            for (int kk = 0; kk < 4; kk++) {
                const uint32_t jsw = (((uint32_t)(kk * 2 + lhalf)) ^ axor) << 4;
                uint32_t Af[2][4], Bf[2][4];
#pragma unroll
                for (int mi = 0; mi < 2; mi++) LDSM4(Af[mi], sA + aoff[mi] + jsw);
#pragma unroll
                for (int p = 0; p < 2; p++) LDSM4(Bf[p], sB + boffb[p] + jsw);
#pragma unroll
                for (int mi = 0; mi < 2; mi++)
#pragma unroll
                    for (int ni = 0; ni < 4; ni++)
                        MMA16816(acc[mi][ni], Af[mi], Bf[ni >> 1][ni & 1], Bf[ni >> 1][(ni & 1) + 2]);
            }
            __syncthreads();   // all warps done with this B slot
            const int ng = g + 4;
            if (tid == 0 && ng < 32) {
                MBAR_EXPECT(bbar + slot * 8, 16384);
                bulk_g2s(sb + SM_B + slot * 16384, bptr + (size_t)ng * 16384, 16384,
                         bbar + slot * 8);
            }
        }

        // ---- epilogue for this n-slice: relu(acc + qb) . w2 -> smem partials ----
        const int nbase = nt * 128 + wn * 32;
        float w2v[8];
#pragma unroll
        for (int ni = 0; ni < 4; ni++)
#pragma unroll
            for (int j = 0; j < 2; j++)
                w2v[ni * 2 + j] = w2p[nbase + ni * 8 + tr * 2 + j];

        if (isdec) {
#pragma unroll
            for (int gidx = 0; gidx < 4; gidx++) {
                const int mi = gidx >> 1, hf = gidx & 1;
                const int rloc = wm * 32 + mi * 16 + hf * 8 + tq;
#pragma unroll
                for (int b = 0; b < B_; b++) {
                    const float* qrow = &qsp[b * H_ + nbase];
                    float s = 0.f;
#pragma unroll
                    for (int ni = 0; ni < 4; ni++)
#pragma unroll
                        for (int j = 0; j < 2; j++) {
                            float v = acc[mi][ni][hf * 2 + j] + qrow[ni * 8 + tr * 2 + j];
                            v = fmaxf(v, 0.f);
                            s = fmaf(v, w2v[ni * 2 + j], s);
                        }
                    s += __shfl_xor_sync(0xffffffffu, s, 1);
                    s += __shfl_xor_sync(0xffffffffu, s, 2);
                    if (tr == 0) atomicAdd(&part[rloc * 8 + b], s);
                }
            }
        } else {
            const int bloc = ((mtile - DECT) * 128) >> 11;   // uniform per tile
            const float* qrow = &qsp[bloc * H_ + nbase];
#pragma unroll
            for (int gidx = 0; gidx < 4; gidx++) {
                const int mi = gidx >> 1, hf = gidx & 1;
                const int rloc = wm * 32 + mi * 16 + hf * 8 + tq;
                float s = 0.f;
#pragma unroll
                for (int ni = 0; ni < 4; ni++)
#pragma unroll
                    for (int j = 0; j < 2; j++) {
                        float v = acc[mi][ni][hf * 2 + j] + qrow[ni * 8 + tr * 2 + j];
                        v = fmaxf(v, 0.f);
                        s = fmaf(v, w2v[ni * 2 + j], s);
                    }
                s += __shfl_xor_sync(0xffffffffu, s, 1);
                s += __shfl_xor_sync(0xffffffffu, s, 2);
                if (tr == 0) atomicAdd(&part[rloc * 8], s);
            }
        }
    }
    __syncthreads();

    // ---- final write (each output element exactly once; mask fused) ----
    if (isdec) {
        for (int idx = tid; idx < 128 * B_; idx += 512) {
            int row = idx >> 3, b = idx & 7;
            out[(size_t)b * OUTC + mtile * 128 + row] = part[idx];
        }
    } else {
        if (tid < 128) {
            int tg = (mtile - DECT) * 128 + tid;
            int bloc = tg >> 11, tt = tg & (T_ - 1);
            float m = mask[tg];
            out[(size_t)bloc * OUTC + V_ + tt] = m * part[tid * 8] - 1000.f * (1.f - m);
        }
    }
}

// ---------------------------------------------------------------------------
// launch: 0=input_embeds 1=target_embeds 2=input_mask 3=w1 4=b1 5=w2 6=decoder_weight
// ---------------------------------------------------------------------------
extern "C" void kernel_launch(void* const* d_in, const int* in_sizes, int n_in,
                              void* d_out, int out_size) {
    const float* in_emb = (const float*)d_in[0];
    const float* tgt    = (const float*)d_in[1];
    const float* mask   = (const float*)d_in[2];
    const float* w1     = (const float*)d_in[3];
    const float* b1     = (const float*)d_in[4];
    const float* w2     = (const float*)d_in[5];
    const float* dec    = (const float*)d_in[6];
    float* out = (float*)d_out;

    static int smem_set = 0;
    if (!smem_set) {
        cudaFuncSetAttribute(main_kernel, cudaFuncAttributeMaxDynamicSharedMemorySize, SMEM_DYN);
        smem_set = 1;
    }

    prep_kernel<<<APREP_BLKS + WPREP_BLKS + QPROJ_BLKS, 256>>>(in_emb, w1, b1, dec, tgt);
    main_kernel<<<MT, 512, SMEM_DYN>>>(mask, w2, out);
}

// round 12
// speedup vs baseline: 4.3067x; 1.2220x over previous
#include <cuda_runtime.h>
#include <cuda_fp16.h>
#include <cstdint>

#define B_   8
#define T_   2048
#define H_   512
#define V_   32000
#define OUTC (V_ + T_)            // 34048
#define NROWS (V_ + B_ * T_)      // 48384
#define MT   (NROWS / 128)        // 378
#define DECT (V_ / 128)           // 250
#define NST  8                    // K chunks of 64

// ---------------- gmem staging (static, no allocs) ----------------
__device__ float g_qb[B_ * H_];                                 // qproj + b1
__device__ __align__(16) unsigned char g_A16[MT][NST][16384];   // 47.25 MB fp16 swizzled
__device__ __align__(16) unsigned char g_B16[4][NST][16384];    // 512 KB fp16 swizzled

// ---------------- helpers ----------------
__device__ __forceinline__ uint32_t smem_u32(const void* p) {
    uint32_t a;
    asm("{ .reg .u64 t; cvta.to.shared.u64 t, %1; cvt.u32.u64 %0, t; }" : "=r"(a) : "l"(p));
    return a;
}
#define SWZ128(o) ((o) ^ (((o) >> 3) & 0x70))

#define MBAR_INIT(a, c) \
    asm volatile("mbarrier.init.shared.b64 [%0], %1;" :: "r"(a), "r"(c) : "memory")
#define MBAR_EXPECT(a, b) \
    asm volatile("mbarrier.arrive.expect_tx.shared.b64 _, [%0], %1;" :: "r"(a), "r"(b) : "memory")
#define MBAR_ARRIVE(a) \
    asm volatile("mbarrier.arrive.shared.b64 _, [%0];" :: "r"(a) : "memory")
#define MBAR_WAIT(a, par) do {                                              \
    asm volatile("{\n\t.reg .pred P;\n\t"                                   \
        "WL%=:\n\t"                                                         \
        "mbarrier.try_wait.parity.acquire.cta.shared::cta.b64 P, [%0], %1, 0x989680;\n\t" \
        "@P bra.uni WD%=;\n\t"                                              \
        "bra.uni WL%=;\n\t"                                                 \
        "WD%=:\n\t}"                                                        \
        :: "r"(a), "r"(par) : "memory");                                    \
} while (0)

__device__ __forceinline__ void bulk_g2s(uint32_t dst, const void* src, uint32_t bytes, uint32_t mbar) {
    asm volatile("cp.async.bulk.shared::cta.global.mbarrier::complete_tx::bytes [%0], [%1], %2, [%3];"
        :: "r"(dst), "l"(src), "r"(bytes), "r"(mbar) : "memory");
}

#define LDSM4(r, a) \
    asm volatile("ldmatrix.sync.aligned.m8n8.x4.shared.b16 {%0,%1,%2,%3}, [%4];" \
        : "=r"((r)[0]), "=r"((r)[1]), "=r"((r)[2]), "=r"((r)[3]) : "r"(a))

#define MMA16816(c, a, b0, b1) \
    asm volatile("mma.sync.aligned.m16n8k16.row.col.f32.f16.f16.f32 " \
        "{%0,%1,%2,%3}, {%4,%5,%6,%7}, {%8,%9}, {%0,%1,%2,%3};" \
        : "+f"((c)[0]), "+f"((c)[1]), "+f"((c)[2]), "+f"((c)[3]) \
        : "r"((a)[0]), "r"((a)[1]), "r"((a)[2]), "r"((a)[3]), "r"(b0), "r"(b1))

// ---------------- main-kernel smem layout (1KB-aligned base) ----------------
#define SM_A     0          // 8 chunks x 16KB = 128KB (full A tile, fp16)
#define SM_B     131072     // 2-stage ring x 32KB (two 128-col slices) = 64KB
#define SM_QB    196608     // 8 x 512 fp32 = 16KB
#define SM_W2    212992     // 512 fp32 = 2KB
#define SM_PART  215040     // 128 rows x 8 b fp32 = 4KB
#define SM_BAR   219136     // abar 8x8B @+0, bfull 2x8B @+64, bempty 2x8B @+80
#define SMEM_DYN (219232 + 1024)

__device__ __forceinline__ uint2 pack4h(float a, float b, float c, float d) {
    __half2 p01(__float2half_rn(a), __float2half_rn(b));
    __half2 p23(__float2half_rn(c), __float2half_rn(d));
    uint2 u;
    u.x = *reinterpret_cast<uint32_t*>(&p01);
    u.y = *reinterpret_cast<uint32_t*>(&p23);
    return u;
}

// ===========================================================================
// Fused prep: [0,6048) aprep (8 rows/blk, MLP=4) | [6048,6112) wprep | [6112,6176) qproj
// ===========================================================================
#define APREP_BLKS 6048
#define WPREP_BLKS 64
#define QPROJ_BLKS 64

__global__ void prep_kernel(const float* __restrict__ in_emb,
                            const float* __restrict__ w1,
                            const float* __restrict__ b1,
                            const float* __restrict__ dec,
                            const float* __restrict__ tgt) {
    __shared__ float sin_[H_];
    __shared__ float sred[256];
    const int bid = blockIdx.x, tid = threadIdx.x;

    if (bid < APREP_BLKS) {
        int r = bid * 8 + (tid >> 5);
        int j0 = tid & 31;
        const float* row = (r < V_) ? (dec + (size_t)r * H_) : (tgt + (size_t)(r - V_) * H_);
        int mt = r >> 7, rl = r & 127;
        float4 v[4];
#pragma unroll
        for (int u = 0; u < 4; u++)
            v[u] = reinterpret_cast<const float4*>(row)[j0 + u * 32];
#pragma unroll
        for (int u = 0; u < 4; u++) {
            int j = j0 + u * 32;
            int s = j >> 4, kl = (j * 4) & 63;
            uint32_t sw = SWZ128((uint32_t)(rl * 128 + kl * 2));
            *reinterpret_cast<uint2*>(&g_A16[mt][s][sw]) = pack4h(v[u].x, v[u].y, v[u].z, v[u].w);
        }
    } else if (bid < APREP_BLKS + WPREP_BLKS) {
        int n = (bid - APREP_BLKS) * 8 + (tid >> 5);
        int j0 = tid & 31;
        const float* row = w1 + (size_t)n * 1024 + 512;
        int nt = n >> 7, nl = n & 127;
        float4 v[4];
#pragma unroll
        for (int u = 0; u < 4; u++)
            v[u] = reinterpret_cast<const float4*>(row)[j0 + u * 32];
#pragma unroll
        for (int u = 0; u < 4; u++) {
            int j = j0 + u * 32;
            int s = j >> 4, kl = (j * 4) & 63;
            uint32_t sw = SWZ128((uint32_t)(nl * 128 + kl * 2));
            *reinterpret_cast<uint2*>(&g_B16[nt][s][sw]) = pack4h(v[u].x, v[u].y, v[u].z, v[u].w);
        }
    } else {
        int q = bid - (APREP_BLKS + WPREP_BLKS);
        int b = q >> 3, kg = q & 7;
        sin_[tid] = in_emb[b * H_ + tid];
        sin_[tid + 256] = in_emb[b * H_ + tid + 256];
        __syncthreads();
        int kq = tid & 63, qq = tid >> 6;
        int k = kg * 64 + kq;
        const float4* wr = reinterpret_cast<const float4*>(w1 + (size_t)k * 1024) + qq * 32;
        const float4* sv = reinterpret_cast<const float4*>(sin_) + qq * 32;
        float acc = 0.f;
#pragma unroll 8
        for (int i = 0; i < 32; i++) {
            float4 w = wr[i], x = sv[i];
            acc += w.x * x.x + w.y * x.y + w.z * x.z + w.w * x.w;
        }
        sred[tid] = acc;
        __syncthreads();
        if (qq == 0)
            g_qb[b * H_ + k] = sred[kq] + sred[kq + 64] + sred[kq + 128] + sred[kq + 192] + b1[k];
    }
}

// ===========================================================================
// Main: one CTA (512 threads, 16 warps) per 128-row M-tile. Full A resident.
// 2 passes over N (128x256 each); warp tile 32x64 (4m x 4n warps).
// B via 2-stage x 32KB mbarrier ring (producer tid0 / consumer warps, no
// full-CTA barriers in the mainloop). Epilogue reduces over N in-CTA.
// ===========================================================================
__global__ __launch_bounds__(512, 1)
void main_kernel(const float* __restrict__ mask,
                 const float* __restrict__ w2,
                 float* __restrict__ out) {
    extern __shared__ unsigned char smraw[];
    uint32_t sb0 = smem_u32(smraw);
    uint32_t sb = (sb0 + 1023) & ~1023u;
    unsigned char* dyn = smraw + (sb - sb0);

    const int tid = threadIdx.x;
    const int lane = tid & 31, wid = tid >> 5;
    const int wm = wid & 3, wn = wid >> 2;           // 4(m) x 4(n), warp tile 32x64
    const int mtile = blockIdx.x;
    const bool isdec = (mtile < DECT);

    const int lrow = lane & 15, lhalf = lane >> 4;
    uint32_t jsw[4];
#pragma unroll
    for (int kk = 0; kk < 4; kk++)
        jsw[kk] = (((uint32_t)(kk * 2 + lhalf)) ^ (uint32_t)(lrow & 7)) << 4;
    uint32_t aoff[2], boff[4];
#pragma unroll
    for (int mi = 0; mi < 2; mi++) aoff[mi] = (uint32_t)((wm * 32 + mi * 16 + lrow) * 128);
#pragma unroll
    for (int pb = 0; pb < 4; pb++) boff[pb] = (uint32_t)(((wn & 1) * 64 + pb * 16 + lrow) * 128);

    const uint32_t abar   = sb + SM_BAR;
    const uint32_t bfull  = sb + SM_BAR + 64;
    const uint32_t bempty = sb + SM_BAR + 80;
    const unsigned char* aptr = &g_A16[mtile][0][0];

    float* qsp = (float*)(dyn + SM_QB);
    float* w2p = (float*)(dyn + SM_W2);
    float* part = (float*)(dyn + SM_PART);

    if (tid == 0) {
#pragma unroll
        for (int s = 0; s < NST; s++) MBAR_INIT(abar + s * 8, 1);
#pragma unroll
        for (int g = 0; g < 2; g++) { MBAR_INIT(bfull + g * 8, 1); MBAR_INIT(bempty + g * 8, 16); }
#pragma unroll
        for (int s = 0; s < NST; s++) {
            MBAR_EXPECT(abar + s * 8, 16384);
            bulk_g2s(sb + SM_A + s * 16384, aptr + (size_t)s * 16384, 16384, abar + s * 8);
        }
        // prime B stages 0,1 (steps g=0,1): stage g holds slices (0,g-chunk) pair
#pragma unroll
        for (int g = 0; g < 2; g++) {
            MBAR_EXPECT(bfull + g * 8, 32768);
            bulk_g2s(sb + SM_B + g * 32768,         &g_B16[0][g][0], 16384, bfull + g * 8);
            bulk_g2s(sb + SM_B + g * 32768 + 16384, &g_B16[1][g][0], 16384, bfull + g * 8);
        }
    }
    // stage qb + w2 + zero partials (overlaps with copies)
    for (int i = tid; i < B_ * H_; i += 512) qsp[i] = g_qb[i];
    if (tid < H_) w2p[tid] = w2[tid];
    for (int i = tid; i < 128 * B_; i += 512) part[i] = 0.f;
    __syncthreads();   // bars initialized + smem staged before any wait

    const int tq = lane >> 2, tr = lane & 3;
    const int bsel = (wn >> 1) * 16384;              // which 128-col slice in stage

    for (int p = 0; p < 2; p++) {
        float acc[2][8][4];
#pragma unroll
        for (int mi = 0; mi < 2; mi++)
#pragma unroll
            for (int ni = 0; ni < 8; ni++)
#pragma unroll
                for (int x = 0; x < 4; x++) acc[mi][ni][x] = 0.f;

        for (int s = 0; s < NST; s++) {
            const int g = p * NST + s;
            const int slot = g & 1;
            const int par = (g >> 1) & 1;
            if (p == 0) MBAR_WAIT(abar + s * 8, 0);
            MBAR_WAIT(bfull + slot * 8, par);

            const uint32_t sA = sb + SM_A + s * 16384;
            const uint32_t sB = sb + SM_B + slot * 32768 + bsel;
#pragma unroll
            for (int kk = 0; kk < 4; kk++) {
                uint32_t Af[2][4], Bf[4][4];
#pragma unroll
                for (int mi = 0; mi < 2; mi++) LDSM4(Af[mi], sA + aoff[mi] + jsw[kk]);
#pragma unroll
                for (int pb = 0; pb < 4; pb++) LDSM4(Bf[pb], sB + boff[pb] + jsw[kk]);
#pragma unroll
                for (int mi = 0; mi < 2; mi++)
#pragma unroll
                    for (int ni = 0; ni < 8; ni++)
                        MMA16816(acc[mi][ni], Af[mi], Bf[ni >> 1][ni & 1], Bf[ni >> 1][(ni & 1) + 2]);
            }
            __syncwarp();
            if (lane == 0) MBAR_ARRIVE(bempty + slot * 8);   // this warp done with stage

            const int gg = g + 2;
            if (tid == 0 && gg < 16) {
                MBAR_WAIT(bempty + slot * 8, par);           // all 16 warps released it
                const int p2 = gg >> 3, s2 = gg & 7;
                MBAR_EXPECT(bfull + slot * 8, 32768);
                bulk_g2s(sb + SM_B + slot * 32768,         &g_B16[2 * p2][s2][0],     16384, bfull + slot * 8);
                bulk_g2s(sb + SM_B + slot * 32768 + 16384, &g_B16[2 * p2 + 1][s2][0], 16384, bfull + slot * 8);
            }
        }

        // ---- epilogue for this pass: relu(acc + qb) . w2 -> smem partials ----
        const int nbase = p * 256 + wn * 64;
        float w2v[16];
#pragma unroll
        for (int ni = 0; ni < 8; ni++)
#pragma unroll
            for (int j = 0; j < 2; j++)
                w2v[ni * 2 + j] = w2p[nbase + ni * 8 + tr * 2 + j];

        const int nb = isdec ? B_ : 1;
        const int bfix = isdec ? 0 : (((mtile - DECT) * 128) >> 11);
        for (int bi = 0; bi < nb; bi++) {
            const int b = isdec ? bi : bfix;
            const float* qrow = &qsp[b * H_ + nbase];
            float qv[16];
#pragma unroll
            for (int ni = 0; ni < 8; ni++)
#pragma unroll
                for (int j = 0; j < 2; j++)
                    qv[ni * 2 + j] = qrow[ni * 8 + tr * 2 + j];
#pragma unroll
            for (int gidx = 0; gidx < 4; gidx++) {
                const int mi = gidx >> 1, hf = gidx & 1;
                const int rloc = wm * 32 + mi * 16 + hf * 8 + tq;
                float s = 0.f;
#pragma unroll
                for (int ni = 0; ni < 8; ni++)
#pragma unroll
                    for (int j = 0; j < 2; j++) {
                        float v = acc[mi][ni][hf * 2 + j] + qv[ni * 2 + j];
                        v = fmaxf(v, 0.f);
                        s = fmaf(v, w2v[ni * 2 + j], s);
                    }
                s += __shfl_xor_sync(0xffffffffu, s, 1);
                s += __shfl_xor_sync(0xffffffffu, s, 2);
                if (tr == 0) atomicAdd(&part[rloc * 8 + (isdec ? b : 0)], s);
            }
        }
    }
    __syncthreads();

    // ---- final write (each output element exactly once; mask fused) ----
    if (isdec) {
        for (int idx = tid; idx < 128 * B_; idx += 512) {
            int row = idx >> 3, b = idx & 7;
            out[(size_t)b * OUTC + mtile * 128 + row] = part[idx];
        }
    } else {
        if (tid < 128) {
            int tg = (mtile - DECT) * 128 + tid;
            int bloc = tg >> 11, tt = tg & (T_ - 1);
            float m = mask[tg];
            out[(size_t)bloc * OUTC + V_ + tt] = m * part[tid * 8] - 1000.f * (1.f - m);
        }
    }
}

// ---------------------------------------------------------------------------
// launch: 0=input_embeds 1=target_embeds 2=input_mask 3=w1 4=b1 5=w2 6=decoder_weight
// ---------------------------------------------------------------------------
extern "C" void kernel_launch(void* const* d_in, const int* in_sizes, int n_in,
                              void* d_out, int out_size) {
    const float* in_emb = (const float*)d_in[0];
    const float* tgt    = (const float*)d_in[1];
    const float* mask   = (const float*)d_in[2];
    const float* w1     = (const float*)d_in[3];
    const float* b1     = (const float*)d_in[4];
    const float* w2     = (const float*)d_in[5];
    const float* dec    = (const float*)d_in[6];
    float* out = (float*)d_out;

    static int smem_set = 0;
    if (!smem_set) {
        cudaFuncSetAttribute(main_kernel, cudaFuncAttributeMaxDynamicSharedMemorySize, SMEM_DYN);
        smem_set = 1;
    }

    prep_kernel<<<APREP_BLKS + WPREP_BLKS + QPROJ_BLKS, 256>>>(in_emb, w1, b1, dec, tgt);
    main_kernel<<<MT, 512, SMEM_DYN>>>(mask, w2, out);
}

// round 13
// speedup vs baseline: 5.2596x; 1.2213x over previous
#include <cuda_runtime.h>
#include <cuda_fp16.h>
#include <cstdint>

#define B_   8
#define T_   2048
#define H_   512
#define V_   32000
#define OUTC (V_ + T_)            // 34048
#define NROWS (V_ + B_ * T_)      // 48384
#define MT64 (NROWS / 64)         // 756 M-tiles of 64 rows
#define DEC64 (V_ / 64)           // 500 decoder tiles
#define NST  8                    // K chunks of 64

// ---------------- gmem staging (static, no allocs) ----------------
__device__ float g_qb[B_ * H_];                                 // qproj + b1
__device__ __align__(16) unsigned char g_A16[MT64][NST][8192];  // 47.25 MB fp16 swizzled (64-row tiles)
__device__ __align__(16) unsigned char g_B16[4][NST][16384];    // 512 KB fp16 swizzled

// ---------------- helpers ----------------
__device__ __forceinline__ uint32_t smem_u32(const void* p) {
    uint32_t a;
    asm("{ .reg .u64 t; cvta.to.shared.u64 t, %1; cvt.u32.u64 %0, t; }" : "=r"(a) : "l"(p));
    return a;
}
#define SWZ128(o) ((o) ^ (((o) >> 3) & 0x70))

#define MBAR_INIT(a, c) \
    asm volatile("mbarrier.init.shared.b64 [%0], %1;" :: "r"(a), "r"(c) : "memory")
#define MBAR_EXPECT(a, b) \
    asm volatile("mbarrier.arrive.expect_tx.shared.b64 _, [%0], %1;" :: "r"(a), "r"(b) : "memory")
#define MBAR_ARRIVE(a) \
    asm volatile("mbarrier.arrive.shared.b64 _, [%0];" :: "r"(a) : "memory")
#define MBAR_WAIT(a, par) do {                                              \
    asm volatile("{\n\t.reg .pred P;\n\t"                                   \
        "WL%=:\n\t"                                                         \
        "mbarrier.try_wait.parity.acquire.cta.shared::cta.b64 P, [%0], %1, 0x989680;\n\t" \
        "@P bra.uni WD%=;\n\t"                                              \
        "bra.uni WL%=;\n\t"                                                 \
        "WD%=:\n\t}"                                                        \
        :: "r"(a), "r"(par) : "memory");                                    \
} while (0)

__device__ __forceinline__ void bulk_g2s(uint32_t dst, const void* src, uint32_t bytes, uint32_t mbar) {
    asm volatile("cp.async.bulk.shared::cta.global.mbarrier::complete_tx::bytes [%0], [%1], %2, [%3];"
        :: "r"(dst), "l"(src), "r"(bytes), "r"(mbar) : "memory");
}

#define LDSM4(r, a) \
    asm volatile("ldmatrix.sync.aligned.m8n8.x4.shared.b16 {%0,%1,%2,%3}, [%4];" \
        : "=r"((r)[0]), "=r"((r)[1]), "=r"((r)[2]), "=r"((r)[3]) : "r"(a))

#define MMA16816(c, a, b0, b1) \
    asm volatile("mma.sync.aligned.m16n8k16.row.col.f32.f16.f16.f32 " \
        "{%0,%1,%2,%3}, {%4,%5,%6,%7}, {%8,%9}, {%0,%1,%2,%3};" \
        : "+f"((c)[0]), "+f"((c)[1]), "+f"((c)[2]), "+f"((c)[3]) \
        : "r"((a)[0]), "r"((a)[1]), "r"((a)[2]), "r"((a)[3]), "r"(b0), "r"(b1))

// ---------------- main-kernel smem layout (1KB-aligned base) ----------------
// stage = [A 8KB][Bslice0 16KB][Bslice1 16KB] = 40960; 2 stages
#define SM_RING  0
#define STAGE_SZ 40960
#define SM_QH    81920      // 8 x 512 fp16 = 8KB
#define SM_W2H   90112      // 512 fp16 = 1KB
#define SM_PART  91136      // 64 rows x 8 b fp32 = 2KB
#define SM_BAR   93184      // bfull 2x8B @+0, bempty 2x8B @+16
#define SMEM_DYN (93184 + 32 + 1024)

__device__ __forceinline__ uint2 pack4h(float a, float b, float c, float d) {
    __half2 p01(__float2half_rn(a), __float2half_rn(b));
    __half2 p23(__float2half_rn(c), __float2half_rn(d));
    uint2 u;
    u.x = *reinterpret_cast<uint32_t*>(&p01);
    u.y = *reinterpret_cast<uint32_t*>(&p23);
    return u;
}
__device__ __forceinline__ uint32_t h2u(__half2 h) { return *reinterpret_cast<uint32_t*>(&h); }

// ===========================================================================
// Fused prep: [0,6048) aprep (8 rows/blk, MLP=4) | [6048,6112) wprep | [6112,6176) qproj
// ===========================================================================
#define APREP_BLKS 6048
#define WPREP_BLKS 64
#define QPROJ_BLKS 64

__global__ void prep_kernel(const float* __restrict__ in_emb,
                            const float* __restrict__ w1,
                            const float* __restrict__ b1,
                            const float* __restrict__ dec,
                            const float* __restrict__ tgt) {
    __shared__ float sin_[H_];
    __shared__ float sred[256];
    const int bid = blockIdx.x, tid = threadIdx.x;

    if (bid < APREP_BLKS) {
        int r = bid * 8 + (tid >> 5);
        int j0 = tid & 31;
        const float* row = (r < V_) ? (dec + (size_t)r * H_) : (tgt + (size_t)(r - V_) * H_);
        int mt = r >> 6, rl = r & 63;
        float4 v[4];
#pragma unroll
        for (int u = 0; u < 4; u++)
            v[u] = reinterpret_cast<const float4*>(row)[j0 + u * 32];
#pragma unroll
        for (int u = 0; u < 4; u++) {
            int j = j0 + u * 32;
            int s = j >> 4, kl = (j * 4) & 63;
            uint32_t sw = SWZ128((uint32_t)(rl * 128 + kl * 2));
            *reinterpret_cast<uint2*>(&g_A16[mt][s][sw]) = pack4h(v[u].x, v[u].y, v[u].z, v[u].w);
        }
    } else if (bid < APREP_BLKS + WPREP_BLKS) {
        int n = (bid - APREP_BLKS) * 8 + (tid >> 5);
        int j0 = tid & 31;
        const float* row = w1 + (size_t)n * 1024 + 512;
        int nt = n >> 7, nl = n & 127;
        float4 v[4];
#pragma unroll
        for (int u = 0; u < 4; u++)
            v[u] = reinterpret_cast<const float4*>(row)[j0 + u * 32];
#pragma unroll
        for (int u = 0; u < 4; u++) {
            int j = j0 + u * 32;
            int s = j >> 4, kl = (j * 4) & 63;
            uint32_t sw = SWZ128((uint32_t)(nl * 128 + kl * 2));
            *reinterpret_cast<uint2*>(&g_B16[nt][s][sw]) = pack4h(v[u].x, v[u].y, v[u].z, v[u].w);
        }
    } else {
        int q = bid - (APREP_BLKS + WPREP_BLKS);
        int b = q >> 3, kg = q & 7;
        sin_[tid] = in_emb[b * H_ + tid];
        sin_[tid + 256] = in_emb[b * H_ + tid + 256];
        __syncthreads();
        int kq = tid & 63, qq = tid >> 6;
        int k = kg * 64 + kq;
        const float4* wr = reinterpret_cast<const float4*>(w1 + (size_t)k * 1024) + qq * 32;
        const float4* sv = reinterpret_cast<const float4*>(sin_) + qq * 32;
        float acc = 0.f;
#pragma unroll 8
        for (int i = 0; i < 32; i++) {
            float4 w = wr[i], x = sv[i];
            acc += w.x * x.x + w.y * x.y + w.z * x.z + w.w * x.w;
        }
        sred[tid] = acc;
        __syncthreads();
        if (qq == 0)
            g_qb[b * H_ + k] = sred[kq] + sred[kq + 64] + sred[kq + 128] + sred[kq + 192] + b1[k];
    }
}

// ===========================================================================
// Main: 756 CTAs (64-row M-tiles), 256 threads (8 warps = 2m x 4n, warp tile
// 32x64), 2 CTAs/SM. A+B stream through a 2-stage x 40KB ring. Epilogue:
// relu in half2, dot via m16n8k16 MMA against w2-broadcast B fragment.
// ===========================================================================
__global__ __launch_bounds__(256, 2)
void main_kernel(const float* __restrict__ mask,
                 const float* __restrict__ w2,
                 float* __restrict__ out) {
    extern __shared__ unsigned char smraw[];
    uint32_t sb0 = smem_u32(smraw);
    uint32_t sb = (sb0 + 1023) & ~1023u;
    unsigned char* dyn = smraw + (sb - sb0);

    const int tid = threadIdx.x;
    const int lane = tid & 31, wid = tid >> 5;
    const int wm = wid & 1, wn = wid >> 1;           // 2(m) x 4(n), warp tile 32x64
    const int mtile = blockIdx.x;
    const bool isdec = (mtile < DEC64);

    const int lrow = lane & 15, lhalf = lane >> 4;
    uint32_t jsw[4];
#pragma unroll
    for (int kk = 0; kk < 4; kk++)
        jsw[kk] = (((uint32_t)(kk * 2 + lhalf)) ^ (uint32_t)(lrow & 7)) << 4;
    uint32_t aoff[2], boff[4];
#pragma unroll
    for (int mi = 0; mi < 2; mi++) aoff[mi] = (uint32_t)((wm * 32 + mi * 16 + lrow) * 128);
#pragma unroll
    for (int pb = 0; pb < 4; pb++) boff[pb] = (uint32_t)(((wn & 1) * 64 + pb * 16 + lrow) * 128);
    const int bsel = (wn >> 1) * 16384;

    const uint32_t bfull  = sb + SM_BAR;
    const uint32_t bempty = sb + SM_BAR + 16;
    const unsigned char* aptr = &g_A16[mtile][0][0];

    __half*  qh  = (__half*)(dyn + SM_QH);
    __half*  w2h = (__half*)(dyn + SM_W2H);
    float*   part = (float*)(dyn + SM_PART);

    if (tid == 0) {
#pragma unroll
        for (int g = 0; g < 2; g++) { MBAR_INIT(bfull + g * 8, 1); MBAR_INIT(bempty + g * 8, 8); }
        // prime steps g=0,1 (pass 0, chunks 0,1)
#pragma unroll
        for (int g = 0; g < 2; g++) {
            uint32_t stg = sb + SM_RING + g * STAGE_SZ;
            MBAR_EXPECT(bfull + g * 8, STAGE_SZ);
            bulk_g2s(stg,          aptr + (size_t)g * 8192, 8192,  bfull + g * 8);
            bulk_g2s(stg + 8192,   &g_B16[0][g][0],         16384, bfull + g * 8);
            bulk_g2s(stg + 24576,  &g_B16[1][g][0],         16384, bfull + g * 8);
        }
    }
    // stage qb (fp16) + w2 (fp16) + zero partials (overlaps with copies)
    for (int i = tid; i < B_ * H_; i += 256) qh[i] = __float2half_rn(g_qb[i]);
    for (int i = tid; i < H_; i += 256) w2h[i] = __float2half_rn(w2[i]);
    for (int i = tid; i < 64 * B_; i += 256) part[i] = 0.f;
    __syncthreads();   // bars initialized + smem staged before any wait

    const int tq = lane >> 2, tr = lane & 3;
    const __half2 z2 = __half2(__half(0.f), __half(0.f));

    for (int p = 0; p < 2; p++) {
        float acc[2][8][4];
#pragma unroll
        for (int mi = 0; mi < 2; mi++)
#pragma unroll
            for (int ni = 0; ni < 8; ni++)
#pragma unroll
                for (int x = 0; x < 4; x++) acc[mi][ni][x] = 0.f;

        for (int s = 0; s < NST; s++) {
            const int g = p * NST + s;
            const int slot = g & 1;
            const int par = (g >> 1) & 1;
            MBAR_WAIT(bfull + slot * 8, par);

            const uint32_t stg = sb + SM_RING + slot * STAGE_SZ;
            const uint32_t sA = stg;
            const uint32_t sB = stg + 8192 + bsel;
#pragma unroll
            for (int kk = 0; kk < 4; kk++) {
                uint32_t Af[2][4], Bf[4][4];
#pragma unroll
                for (int mi = 0; mi < 2; mi++) LDSM4(Af[mi], sA + aoff[mi] + jsw[kk]);
#pragma unroll
                for (int pb = 0; pb < 4; pb++) LDSM4(Bf[pb], sB + boff[pb] + jsw[kk]);
#pragma unroll
                for (int mi = 0; mi < 2; mi++)
#pragma unroll
                    for (int ni = 0; ni < 8; ni++)
                        MMA16816(acc[mi][ni], Af[mi], Bf[ni >> 1][ni & 1], Bf[ni >> 1][(ni & 1) + 2]);
            }
            __syncwarp();
            if (lane == 0) MBAR_ARRIVE(bempty + slot * 8);   // this warp done with stage

            const int gg = g + 2;
            if (tid == 0 && gg < 16) {
                MBAR_WAIT(bempty + slot * 8, par);           // all 8 warps released it
                const int p2 = gg >> 3, s2 = gg & 7;
                uint32_t stg2 = sb + SM_RING + slot * STAGE_SZ;
                MBAR_EXPECT(bfull + slot * 8, STAGE_SZ);
                bulk_g2s(stg2,         aptr + (size_t)s2 * 8192,   8192,  bfull + slot * 8);
                bulk_g2s(stg2 + 8192,  &g_B16[2 * p2][s2][0],      16384, bfull + slot * 8);
                bulk_g2s(stg2 + 24576, &g_B16[2 * p2 + 1][s2][0],  16384, bfull + slot * 8);
            }
        }

        // ---- epilogue for this pass: relu in half2, dot via MMA vs w2 ----
        const int nbase = p * 256 + wn * 64;

        // acc -> half2: acch[mi][ni][0] = rows tq, cols ni*8+tr*2(+1); [1] = rows tq+8
        __half2 acch[2][8][2];
#pragma unroll
        for (int mi = 0; mi < 2; mi++)
#pragma unroll
            for (int ni = 0; ni < 8; ni++) {
                acch[mi][ni][0] = __floats2half2_rn(acc[mi][ni][0], acc[mi][ni][1]);
                acch[mi][ni][1] = __floats2half2_rn(acc[mi][ni][2], acc[mi][ni][3]);
            }

        // w2 B-fragments (all 8 n-cols identical -> broadcast dot)
        uint32_t bw[4][2];
#pragma unroll
        for (int g2 = 0; g2 < 4; g2++) {
            bw[g2][0] = *reinterpret_cast<const uint32_t*>(w2h + nbase + g2 * 16 + tr * 2);
            bw[g2][1] = *reinterpret_cast<const uint32_t*>(w2h + nbase + g2 * 16 + 8 + tr * 2);
        }

        const int nb = isdec ? B_ : 1;
        const int bfix = isdec ? 0 : (((mtile - DEC64) * 64) >> 11);
        for (int bi = 0; bi < nb; bi++) {
            const int b = isdec ? bi : bfix;
            const __half2* qp = reinterpret_cast<const __half2*>(qh + b * H_ + nbase + tr * 2);
            __half2 qa[4], qb2[4];
#pragma unroll
            for (int g2 = 0; g2 < 4; g2++) { qa[g2] = qp[g2 * 8]; qb2[g2] = qp[g2 * 8 + 4]; }
#pragma unroll
            for (int mi = 0; mi < 2; mi++) {
                float d[4] = {0.f, 0.f, 0.f, 0.f};
#pragma unroll
                for (int g2 = 0; g2 < 4; g2++) {
                    uint32_t fr[4];
                    fr[0] = h2u(__hmax2(__hadd2(acch[mi][2 * g2][0],     qa[g2]),  z2));
                    fr[1] = h2u(__hmax2(__hadd2(acch[mi][2 * g2][1],     qa[g2]),  z2));
                    fr[2] = h2u(__hmax2(__hadd2(acch[mi][2 * g2 + 1][0], qb2[g2]), z2));
                    fr[3] = h2u(__hmax2(__hadd2(acch[mi][2 * g2 + 1][1], qb2[g2]), z2));
                    MMA16816(d, fr, bw[g2][0], bw[g2][1]);
                }
                if (tr == 0) {
                    const int bslot = isdec ? b : 0;
                    atomicAdd(&part[(wm * 32 + mi * 16 + tq) * 8 + bslot],     d[0]);
                    atomicAdd(&part[(wm * 32 + mi * 16 + 8 + tq) * 8 + bslot], d[2]);
                }
            }
        }
    }
    __syncthreads();

    // ---- final write (each output element exactly once; mask fused) ----
    if (isdec) {
        for (int idx = tid; idx < 64 * B_; idx += 256) {
            int row = idx >> 3, b = idx & 7;
            out[(size_t)b * OUTC + mtile * 64 + row] = part[idx];
        }
    } else {
        if (tid < 64) {
            int tg = (mtile - DEC64) * 64 + tid;
            int bloc = tg >> 11, tt = tg & (T_ - 1);
            float m = mask[tg];
            out[(size_t)bloc * OUTC + V_ + tt] = m * part[tid * 8] - 1000.f * (1.f - m);
        }
    }
}

// ---------------------------------------------------------------------------
// launch: 0=input_embeds 1=target_embeds 2=input_mask 3=w1 4=b1 5=w2 6=decoder_weight
// ---------------------------------------------------------------------------
extern "C" void kernel_launch(void* const* d_in, const int* in_sizes, int n_in,
                              void* d_out, int out_size) {
    const float* in_emb = (const float*)d_in[0];
    const float* tgt    = (const float*)d_in[1];
    const float* mask   = (const float*)d_in[2];
    const float* w1     = (const float*)d_in[3];
    const float* b1     = (const float*)d_in[4];
    const float* w2     = (const float*)d_in[5];
    const float* dec    = (const float*)d_in[6];
    float* out = (float*)d_out;

    static int smem_set = 0;
    if (!smem_set) {
        cudaFuncSetAttribute(main_kernel, cudaFuncAttributeMaxDynamicSharedMemorySize, SMEM_DYN);
        smem_set = 1;
    }

    prep_kernel<<<APREP_BLKS + WPREP_BLKS + QPROJ_BLKS, 256>>>(in_emb, w1, b1, dec, tgt);
    main_kernel<<<MT64, 256, SMEM_DYN>>>(mask, w2, out);
}

// round 15
// speedup vs baseline: 5.7014x; 1.0840x over previous
#include <cuda_runtime.h>
#include <cuda_fp16.h>
#include <cstdint>

#define B_   8
#define T_   2048
#define H_   512
#define V_   32000
#define OUTC (V_ + T_)            // 34048
#define NROWS (V_ + B_ * T_)      // 48384
#define MT64 (NROWS / 64)         // 756 M-tiles of 64 rows
#define DEC64 (V_ / 64)           // 500 decoder tiles
#define NST  8                    // K chunks of 64

// ---------------- gmem staging (static, no allocs) ----------------
__device__ float g_qb[B_ * H_];                                 // qproj + b1
__device__ __align__(16) unsigned char g_B16[4][NST][16384];    // 512 KB fp16 swizzled

// ---------------- helpers ----------------
__device__ __forceinline__ uint32_t smem_u32(const void* p) {
    uint32_t a;
    asm("{ .reg .u64 t; cvta.to.shared.u64 t, %1; cvt.u32.u64 %0, t; }" : "=r"(a) : "l"(p));
    return a;
}
#define SWZ128(o) ((o) ^ (((o) >> 3) & 0x70))

#define MBAR_INIT(a, c) \
    asm volatile("mbarrier.init.shared.b64 [%0], %1;" :: "r"(a), "r"(c) : "memory")
#define MBAR_EXPECT(a, b) \
    asm volatile("mbarrier.arrive.expect_tx.shared.b64 _, [%0], %1;" :: "r"(a), "r"(b) : "memory")
#define MBAR_ARRIVE(a) \
    asm volatile("mbarrier.arrive.shared.b64 _, [%0];" :: "r"(a) : "memory")
#define MBAR_WAIT(a, par) do {                                              \
    asm volatile("{\n\t.reg .pred P;\n\t"                                   \
        "WL%=:\n\t"                                                         \
        "mbarrier.try_wait.parity.acquire.cta.shared::cta.b64 P, [%0], %1, 0x989680;\n\t" \
        "@P bra.uni WD%=;\n\t"                                              \
        "bra.uni WL%=;\n\t"                                                 \
        "WD%=:\n\t}"                                                        \
        :: "r"(a), "r"(par) : "memory");                                    \
} while (0)

__device__ __forceinline__ void bulk_g2s(uint32_t dst, const void* src, uint32_t bytes, uint32_t mbar) {
    asm volatile("cp.async.bulk.shared::cta.global.mbarrier::complete_tx::bytes [%0], [%1], %2, [%3];"
        :: "r"(dst), "l"(src), "r"(bytes), "r"(mbar) : "memory");
}

#define LDSM4(r, a) \
    asm volatile("ldmatrix.sync.aligned.m8n8.x4.shared.b16 {%0,%1,%2,%3}, [%4];" \
        : "=r"((r)[0]), "=r"((r)[1]), "=r"((r)[2]), "=r"((r)[3]) : "r"(a))

#define MMA16816(c, a, b0, b1) \
    asm volatile("mma.sync.aligned.m16n8k16.row.col.f32.f16.f16.f32 " \
        "{%0,%1,%2,%3}, {%4,%5,%6,%7}, {%8,%9}, {%0,%1,%2,%3};" \
        : "+f"((c)[0]), "+f"((c)[1]), "+f"((c)[2]), "+f"((c)[3]) \
        : "r"((a)[0]), "r"((a)[1]), "r"((a)[2]), "r"((a)[3]), "r"(b0), "r"(b1))

// ---------------- main-kernel smem layout (1KB-aligned base) ----------------
#define SM_A16   0          // 2-stage x 8KB converted A = 16KB
#define SM_B     16384      // 2-stage x 32KB (two 128-col B slices) = 64KB
#define SM_QH    81920      // 8 x 512 fp16 = 8KB
#define SM_W2H   90112      // 512 fp16 = 1KB
#define SM_PART  91136      // 64 rows x 8 b fp32 = 2KB
#define SM_BAR   93184      // bfull 2x8 @+0, bempty 2x8 @+16, afull 2x8 @+32, aempty 2x8 @+48
#define SMEM_DYN (93248 + 1024)

__device__ __forceinline__ uint2 pack4h(float a, float b, float c, float d) {
    __half2 p01(__float2half_rn(a), __float2half_rn(b));
    __half2 p23(__float2half_rn(c), __float2half_rn(d));
    uint2 u;
    u.x = *reinterpret_cast<uint32_t*>(&p01);
    u.y = *reinterpret_cast<uint32_t*>(&p23);
    return u;
}
__device__ __forceinline__ uint32_t h2u(__half2 h) { return *reinterpret_cast<uint32_t*>(&h); }

// ===========================================================================
// Prep: [0,64) wprep | [64,128) qproj   (A conversion now lives in main)
// ===========================================================================
#define WPREP_BLKS 64
#define QPROJ_BLKS 64

__global__ void prep_kernel(const float* __restrict__ in_emb,
                            const float* __restrict__ w1,
                            const float* __restrict__ b1) {
    __shared__ float sin_[H_];
    __shared__ float sred[256];
    const int bid = blockIdx.x, tid = threadIdx.x;

    if (bid < WPREP_BLKS) {
        int n = bid * 8 + (tid >> 5);
        int j0 = tid & 31;
        const float* row = w1 + (size_t)n * 1024 + 512;
        int nt = n >> 7, nl = n & 127;
        float4 v[4];
#pragma unroll
        for (int u = 0; u < 4; u++)
            v[u] = reinterpret_cast<const float4*>(row)[j0 + u * 32];
#pragma unroll
        for (int u = 0; u < 4; u++) {
            int j = j0 + u * 32;
            int s = j >> 4, kl = (j * 4) & 63;
            uint32_t sw = SWZ128((uint32_t)(nl * 128 + kl * 2));
            *reinterpret_cast<uint2*>(&g_B16[nt][s][sw]) = pack4h(v[u].x, v[u].y, v[u].z, v[u].w);
        }
    } else {
        int q = bid - WPREP_BLKS;
        int b = q >> 3, kg = q & 7;
        sin_[tid] = in_emb[b * H_ + tid];
        sin_[tid + 256] = in_emb[b * H_ + tid + 256];
        __syncthreads();
        int kq = tid & 63, qq = tid >> 6;
        int k = kg * 64 + kq;
        const float4* wr = reinterpret_cast<const float4*>(w1 + (size_t)k * 1024) + qq * 32;
        const float4* sv = reinterpret_cast<const float4*>(sin_) + qq * 32;
        float acc = 0.f;
#pragma unroll 8
        for (int i = 0; i < 32; i++) {
            float4 w = wr[i], x = sv[i];
            acc += w.x * x.x + w.y * x.y + w.z * x.z + w.w * x.w;
        }
        sred[tid] = acc;
        __syncthreads();
        if (qq == 0)
            g_qb[b * H_ + k] = sred[kq] + sred[kq + 64] + sred[kq + 128] + sred[kq + 192] + b1[k];
    }
}

// ===========================================================================
// Main: 756 CTAs (64-row M-tiles), 256 threads (2m x 4n warps, tile 32x64),
// 2 CTAs/SM. A converted fp32->fp16 IN-KERNEL: each warp owns 8 rows; LDG
// issued 2 steps ahead, STS swizzled into 2-stage A buffer (afull/aempty
// mbarriers). B streams via 2-stage bulk ring. Epilogue: half2 relu + MMA dot.
// ===========================================================================
__global__ __launch_bounds__(256, 2)
void main_kernel(const float* __restrict__ mask,
                 const float* __restrict__ w2,
                 const float* __restrict__ dec,
                 const float* __restrict__ tgt,
                 float* __restrict__ out) {
    extern __shared__ unsigned char smraw[];
    uint32_t sb0 = smem_u32(smraw);
    uint32_t sb = (sb0 + 1023) & ~1023u;
    unsigned char* dyn = smraw + (sb - sb0);

    const int tid = threadIdx.x;
    const int lane = tid & 31, wid = tid >> 5;
    const int wm = wid & 1, wn = wid >> 1;           // 2(m) x 4(n), warp tile 32x64
    const int mtile = blockIdx.x;
    const bool isdec = (mtile < DEC64);

    const int lrow = lane & 15, lhalf = lane >> 4;
    uint32_t jsw[4];
#pragma unroll
    for (int kk = 0; kk < 4; kk++)
        jsw[kk] = (((uint32_t)(kk * 2 + lhalf)) ^ (uint32_t)(lrow & 7)) << 4;
    uint32_t aoff[2], boff[4];
#pragma unroll
    for (int mi = 0; mi < 2; mi++) aoff[mi] = (uint32_t)((wm * 32 + mi * 16 + lrow) * 128);
#pragma unroll
    for (int pb = 0; pb < 4; pb++) boff[pb] = (uint32_t)(((wn & 1) * 64 + pb * 16 + lrow) * 128);
    const int bsel = (wn >> 1) * 16384;

    const uint32_t bfull  = sb + SM_BAR;
    const uint32_t bempty = sb + SM_BAR + 16;
    const uint32_t afull  = sb + SM_BAR + 32;
    const uint32_t aempty = sb + SM_BAR + 48;

    __half* qh   = (__half*)(dyn + SM_QH);
    __half* w2h  = (__half*)(dyn + SM_W2H);
    float*  part = (float*)(dyn + SM_PART);
    unsigned char* a16p = dyn + SM_A16;

    // ---- per-lane A-conversion geometry: warp owns rows [wid*8, wid*8+8) ----
    const int rl = (wid << 3) + (lane >> 2);        // row in tile 0..63
    const int j0 = lane & 3;                        // float4 column group
    const int row_g = mtile * 64 + rl;
    const float* arow = (row_g < V_) ? (dec + (size_t)row_g * H_)
                                     : (tgt + (size_t)(row_g - V_) * H_);
    uint32_t swoff[4];
#pragma unroll
    for (int u = 0; u < 4; u++)
        swoff[u] = SWZ128((uint32_t)(rl * 128 + 8 * (j0 + 4 * u)));

    if (tid == 0) {
#pragma unroll
        for (int g = 0; g < 2; g++) {
            MBAR_INIT(bfull + g * 8, 1);  MBAR_INIT(bempty + g * 8, 8);
            MBAR_INIT(afull + g * 8, 8);  MBAR_INIT(aempty + g * 8, 8);
        }
    }
    __syncthreads();                                 // barriers visible to all

    if (tid == 0) {
#pragma unroll
        for (int g = 0; g < 2; g++) {
            uint32_t stg = sb + SM_B + g * 32768;
            MBAR_EXPECT(bfull + g * 8, 32768);
            bulk_g2s(stg,         &g_B16[0][g][0], 16384, bfull + g * 8);
            bulk_g2s(stg + 16384, &g_B16[1][g][0], 16384, bfull + g * 8);
        }
    }
    // prime A chunks 0,1 (convert fp32 -> swizzled fp16)
#pragma unroll
    for (int c = 0; c < 2; c++) {
        const float4* pA = reinterpret_cast<const float4*>(arow + c * 64);
#pragma unroll
        for (int u = 0; u < 4; u++) {
            float4 v = pA[j0 + 4 * u];
            *reinterpret_cast<uint2*>(a16p + c * 8192 + swoff[u]) = pack4h(v.x, v.y, v.z, v.w);
        }
        __syncwarp();
        if (lane == 0) MBAR_ARRIVE(afull + c * 8);
    }
    // stage qb (fp16) + w2 (fp16) + zero partials (overlaps with B copies)
    for (int i = tid; i < B_ * H_; i += 256) qh[i] = __float2half_rn(g_qb[i]);
    for (int i = tid; i < H_; i += 256) w2h[i] = __float2half_rn(w2[i]);
    for (int i = tid; i < 64 * B_; i += 256) part[i] = 0.f;

    const int tq = lane >> 2, tr = lane & 3;
    const __half2 z2 = __half2(__half(0.f), __half(0.f));

    for (int p = 0; p < 2; p++) {
        float acc[2][8][4];
#pragma unroll
        for (int mi = 0; mi < 2; mi++)
#pragma unroll
            for (int ni = 0; ni < 8; ni++)
#pragma unroll
                for (int x = 0; x < 4; x++) acc[mi][ni][x] = 0.f;

        for (int s = 0; s < NST; s++) {
            const int g = p * NST + s;
            const int slot = g & 1;
            const int par = (g >> 1) & 1;
            const int gg = g + 2;

            MBAR_WAIT(afull + slot * 8, par);
            MBAR_WAIT(bfull + slot * 8, par);

            // (b) prefetch raw fp32 A for step g+2 (chunk gg&7); latency hidden by MMAs
            float4 av[4];
            if (gg < 16) {
                const float4* pA = reinterpret_cast<const float4*>(arow + (gg & 7) * 64);
#pragma unroll
                for (int u = 0; u < 4; u++) av[u] = pA[j0 + 4 * u];
            }

            const uint32_t sA = sb + SM_A16 + slot * 8192;
            const uint32_t sB = sb + SM_B + slot * 32768 + bsel;
#pragma unroll
            for (int kk = 0; kk < 4; kk++) {
                uint32_t Af[2][4], Bf[4][4];
#pragma unroll
                for (int mi = 0; mi < 2; mi++) LDSM4(Af[mi], sA + aoff[mi] + jsw[kk]);
#pragma unroll
                for (int pb = 0; pb < 4; pb++) LDSM4(Bf[pb], sB + boff[pb] + jsw[kk]);
#pragma unroll
                for (int mi = 0; mi < 2; mi++)
#pragma unroll
                    for (int ni = 0; ni < 8; ni++)
                        MMA16816(acc[mi][ni], Af[mi], Bf[ni >> 1][ni & 1], Bf[ni >> 1][(ni & 1) + 2]);
            }
            __syncwarp();
            if (lane == 0) { MBAR_ARRIVE(aempty + slot * 8); MBAR_ARRIVE(bempty + slot * 8); }

            if (gg < 16) {
                // (e) convert + store A for step g+2 once all warps drained the slot
                MBAR_WAIT(aempty + slot * 8, par);
#pragma unroll
                for (int u = 0; u < 4; u++)
                    *reinterpret_cast<uint2*>(a16p + slot * 8192 + swoff[u]) =
                        pack4h(av[u].x, av[u].y, av[u].z, av[u].w);
                __syncwarp();
                if (lane == 0) MBAR_ARRIVE(afull + slot * 8);

                // (f) B refill by tid0
                if (tid == 0) {
                    MBAR_WAIT(bempty + slot * 8, par);
                    const int p2 = gg >> 3, s2 = gg & 7;
                    uint32_t stg2 = sb + SM_B + slot * 32768;
                    MBAR_EXPECT(bfull + slot * 8, 32768);
                    bulk_g2s(stg2,         &g_B16[2 * p2][s2][0],     16384, bfull + slot * 8);
                    bulk_g2s(stg2 + 16384, &g_B16[2 * p2 + 1][s2][0], 16384, bfull + slot * 8);
                }
            }
        }

        // ---- epilogue for this pass: relu in half2, dot via MMA vs w2 ----
        const int nbase = p * 256 + wn * 64;

        __half2 acch[2][8][2];
#pragma unroll
        for (int mi = 0; mi < 2; mi++)
#pragma unroll
            for (int ni = 0; ni < 8; ni++) {
                acch[mi][ni][0] = __floats2half2_rn(acc[mi][ni][0], acc[mi][ni][1]);
                acch[mi][ni][1] = __floats2half2_rn(acc[mi][ni][2], acc[mi][ni][3]);
            }

        uint32_t bw[4][2];
#pragma unroll
        for (int g2 = 0; g2 < 4; g2++) {
            bw[g2][0] = *reinterpret_cast<const uint32_t*>(w2h + nbase + g2 * 16 + tr * 2);
            bw[g2][1] = *reinterpret_cast<const uint32_t*>(w2h + nbase + g2 * 16 + 8 + tr * 2);
        }

        const int nb = isdec ? B_ : 1;
        const int bfix = isdec ? 0 : (((mtile - DEC64) * 64) >> 11);
        for (int bi = 0; bi < nb; bi++) {
            const int b = isdec ? bi : bfix;
            const __half2* qp = reinterpret_cast<const __half2*>(qh + b * H_ + nbase + tr * 2);
            __half2 qa[4], qb2[4];
#pragma unroll
            for (int g2 = 0; g2 < 4; g2++) { qa[g2] = qp[g2 * 8]; qb2[g2] = qp[g2 * 8 + 4]; }
#pragma unroll
            for (int mi = 0; mi < 2; mi++) {
                float d[4] = {0.f, 0.f, 0.f, 0.f};
#pragma unroll
                for (int g2 = 0; g2 < 4; g2++) {
                    uint32_t fr[4];
                    fr[0] = h2u(__hmax2(__hadd2(acch[mi][2 * g2][0],     qa[g2]),  z2));
                    fr[1] = h2u(__hmax2(__hadd2(acch[mi][2 * g2][1],     qa[g2]),  z2));
                    fr[2] = h2u(__hmax2(__hadd2(acch[mi][2 * g2 + 1][0], qb2[g2]), z2));
                    fr[3] = h2u(__hmax2(__hadd2(acch[mi][2 * g2 + 1][1], qb2[g2]), z2));
                    MMA16816(d, fr, bw[g2][0], bw[g2][1]);
                }
                if (tr == 0) {
                    const int bslot = isdec ? b : 0;
                    atomicAdd(&part[(wm * 32 + mi * 16 + tq) * 8 + bslot],     d[0]);
                    atomicAdd(&part[(wm * 32 + mi * 16 + 8 + tq) * 8 + bslot], d[2]);
                }
            }
        }
    }
    __syncthreads();

    // ---- final write (each output element exactly once; mask fused) ----
    if (isdec) {
        for (int idx = tid; idx < 64 * B_; idx += 256) {
            int row = idx >> 3, b = idx & 7;
            out[(size_t)b * OUTC + mtile * 64 + row] = part[idx];
        }
    } else {
        if (tid < 64) {
            int tg = (mtile - DEC64) * 64 + tid;
            int bloc = tg >> 11, tt = tg & (T_ - 1);
            float m = mask[tg];
            out[(size_t)bloc * OUTC + V_ + tt] = m * part[tid * 8] - 1000.f * (1.f - m);
        }
    }
}

// ---------------------------------------------------------------------------
// launch: 0=input_embeds 1=target_embeds 2=input_mask 3=w1 4=b1 5=w2 6=decoder_weight
// ---------------------------------------------------------------------------
extern "C" void kernel_launch(void* const* d_in, const int* in_sizes, int n_in,
                              void* d_out, int out_size) {
    const float* in_emb = (const float*)d_in[0];
    const float* tgt    = (const float*)d_in[1];
    const float* mask   = (const float*)d_in[2];
    const float* w1     = (const float*)d_in[3];
    const float* b1     = (const float*)d_in[4];
    const float* w2     = (const float*)d_in[5];
    const float* dec    = (const float*)d_in[6];
    float* out = (float*)d_out;

    static int smem_set = 0;
    if (!smem_set) {
        cudaFuncSetAttribute(main_kernel, cudaFuncAttributeMaxDynamicSharedMemorySize, SMEM_DYN);
        smem_set = 1;
    }

    prep_kernel<<<WPREP_BLKS + QPROJ_BLKS, 256>>>(in_emb, w1, b1);
    main_kernel<<<MT64, 256, SMEM_DYN>>>(mask, w2, dec, tgt, out);
}